// round 11
// baseline (speedup 1.0000x reference)
#include <cuda_runtime.h>
#include <cuda_bf16.h>
#include <cstdint>

#define CC 4
#define LL 1024
#define HH 8
#define DD 64
#define TT (CC*LL)
#define QSCALE 0.125f
#define EPSV 1e-6f
#define PTOT 2176   // 2080 unique (d<=e) pairs + 96 pad
#define PREAL 2080

// Scratch (static __device__ — no allocation allowed)
__device__ float g_buf[CC*HH*LL];
__device__ float P_buf[(size_t)3*HH*PTOT*DD];
__device__ float z_buf[3*HH*PTOT];
__device__ float zs_buf[3*HH*PTOT];
__device__ float row_buf[TT*HH];
__device__ short2 lut_de[PTOT];
__device__ __nv_bfloat16 Qsh_g[(size_t)TT*HH*DD], Qsl_g[(size_t)TT*HH*DD];
__device__ __nv_bfloat16 Ksh_g[(size_t)TT*HH*DD], Ksl_g[(size_t)TT*HH*DD];
__device__ __nv_bfloat16 Vsh_g[(size_t)TT*HH*DD], Vsl_g[(size_t)TT*HH*DD];
__device__ __nv_bfloat16 Sh_g[(size_t)3*HH*PTOT*DD], Sl_g[(size_t)3*HH*PTOT*DD];

// ---------------------------------------------------------------------------
// mma.sync helpers
// ---------------------------------------------------------------------------
__device__ __forceinline__ uint32_t smem_u32(const void* p) {
    uint32_t a;
    asm("{ .reg .u64 t; cvta.to.shared.u64 t, %1; cvt.u32.u64 %0, t; }"
        : "=r"(a) : "l"(p));
    return a;
}
__device__ __forceinline__ void ldsm4(uint32_t* r, uint32_t a) {
    asm volatile("ldmatrix.sync.aligned.m8n8.x4.shared.b16 {%0,%1,%2,%3}, [%4];"
        : "=r"(r[0]), "=r"(r[1]), "=r"(r[2]), "=r"(r[3]) : "r"(a));
}
__device__ __forceinline__ void ldsm4t(uint32_t* r, uint32_t a) {
    asm volatile("ldmatrix.sync.aligned.m8n8.x4.trans.shared.b16 {%0,%1,%2,%3}, [%4];"
        : "=r"(r[0]), "=r"(r[1]), "=r"(r[2]), "=r"(r[3]) : "r"(a));
}
__device__ __forceinline__ void mma16816(float* d, const uint32_t* a, const uint32_t* b) {
    asm volatile("mma.sync.aligned.m16n8k16.row.col.f32.bf16.bf16.f32 "
        "{%0,%1,%2,%3}, {%4,%5,%6,%7}, {%8,%9}, {%0,%1,%2,%3};"
        : "+f"(d[0]), "+f"(d[1]), "+f"(d[2]), "+f"(d[3])
        : "r"(a[0]), "r"(a[1]), "r"(a[2]), "r"(a[3]), "r"(b[0]), "r"(b[1]));
}
__device__ __forceinline__ void mma16816s(float* d, const uint32_t* a,
                                          uint32_t b0, uint32_t b1) {
    asm volatile("mma.sync.aligned.m16n8k16.row.col.f32.bf16.bf16.f32 "
        "{%0,%1,%2,%3}, {%4,%5,%6,%7}, {%8,%9}, {%0,%1,%2,%3};"
        : "+f"(d[0]), "+f"(d[1]), "+f"(d[2]), "+f"(d[3])
        : "r"(a[0]), "r"(a[1]), "r"(a[2]), "r"(a[3]), "r"(b0), "r"(b1));
}
__device__ __forceinline__ void split_st(__nv_bfloat16* hb, __nv_bfloat16* lb,
                                         int idx, float a) {
    __nv_bfloat16 hv = __float2bfloat16(a);
    hb[idx] = hv;
    lb[idx] = __float2bfloat16(a - __bfloat162float(hv));
}
__device__ __forceinline__ void split2(float x, float y, uint32_t& hi, uint32_t& lo) {
    __nv_bfloat16 xh = __float2bfloat16(x), yh = __float2bfloat16(y);
    __nv_bfloat16 xl = __float2bfloat16(x - __bfloat162float(xh));
    __nv_bfloat16 yl = __float2bfloat16(y - __bfloat162float(yh));
    hi = (uint32_t)*(uint16_t*)&xh | ((uint32_t)*(uint16_t*)&yh << 16);
    lo = (uint32_t)*(uint16_t*)&xl | ((uint32_t)*(uint16_t*)&yl << 16);
}

// ---------------------------------------------------------------------------
// K0a: pre-split Q*scale, K, V into global bf16 hi/lo, [h][t][d] layout.
// ---------------------------------------------------------------------------
__global__ void split_kernel(const float* __restrict__ q,
                             const float* __restrict__ k,
                             const float* __restrict__ v) {
    const int t0 = blockIdx.x * 64, h = blockIdx.y;
    for (int idx = threadIdx.x; idx < 1024; idx += 256) {
        const int l = idx >> 4, d4 = (idx & 15) << 2;
        const int t = t0 + l;
        const size_t gi = ((size_t)t * HH + h) * DD + d4;
        const size_t oo = ((size_t)h * TT + t) * DD + d4;
        uint32_t a0, b0, a1, b1;
        const float4 qv = *(const float4*)&q[gi];
        split2(qv.x * QSCALE, qv.y * QSCALE, a0, b0);
        split2(qv.z * QSCALE, qv.w * QSCALE, a1, b1);
        *(uint2*)&Qsh_g[oo] = make_uint2(a0, a1);
        *(uint2*)&Qsl_g[oo] = make_uint2(b0, b1);
        const float4 kv = *(const float4*)&k[gi];
        split2(kv.x, kv.y, a0, b0);
        split2(kv.z, kv.w, a1, b1);
        *(uint2*)&Ksh_g[oo] = make_uint2(a0, a1);
        *(uint2*)&Ksl_g[oo] = make_uint2(b0, b1);
        const float4 vv = *(const float4*)&v[gi];
        split2(vv.x, vv.y, a0, b0);
        split2(vv.z, vv.w, a1, b1);
        *(uint2*)&Vsh_g[oo] = make_uint2(a0, a1);
        *(uint2*)&Vsl_g[oo] = make_uint2(b0, b1);
    }
}

// ---------------------------------------------------------------------------
// K0b: cumsum per (c,h) + pair-LUT build (last block)
// ---------------------------------------------------------------------------
__global__ void init_kernel(const float* __restrict__ lg) {
    if (blockIdx.x == CC * HH) {
        for (int p = threadIdx.x; p < PTOT; p += 256) {
            short d = 0, e = 0;
            if (p < PREAL) {
                int off = 0, dd = 0;
                while (off + (DD - dd) <= p) { off += DD - dd; dd++; }
                d = (short)dd; e = (short)(dd + (p - off));
            }
            lut_de[p] = make_short2(d, e);
        }
        return;
    }
    int c = blockIdx.x / HH, h = blockIdx.x % HH;
    int t = threadIdx.x;
    float vloc[4];
    float s = 0.f;
#pragma unroll
    for (int i = 0; i < 4; i++) {
        int l = t * 4 + i;
        s += lg[(c * LL + l) * HH + h];
        vloc[i] = s;
    }
    float tot = s;
#pragma unroll
    for (int off = 1; off < 32; off <<= 1) {
        float n = __shfl_up_sync(0xffffffffu, tot, off);
        if ((t & 31) >= off) tot += n;
    }
    __shared__ float wsum[8];
    __shared__ float woff[8];
    if ((t & 31) == 31) wsum[t >> 5] = tot;
    __syncthreads();
    if (t == 0) {
        float a = 0.f;
        for (int w = 0; w < 8; w++) { woff[w] = a; a += wsum[w]; }
    }
    __syncthreads();
    float ex = woff[t >> 5] + (tot - s);
#pragma unroll
    for (int i = 0; i < 4; i++)
        g_buf[(c * HH + h) * LL + t * 4 + i] = ex + vloc[i];
}

// ---------------------------------------------------------------------------
// K1: intra-chunk causal attention via bf16-split mma.sync.
// Heavy tiles launch first (tile = 15 - blockIdx.x) for wave packing.
// ---------------------------------------------------------------------------
__global__ void __launch_bounds__(128) intra_tc_kernel(float* __restrict__ out) {
    __shared__ __align__(16) __nv_bfloat16 Qh[64 * 72], Ql[64 * 72];
    __shared__ __align__(16) __nv_bfloat16 Kh[32 * 72], Kl[32 * 72];
    __shared__ __align__(16) __nv_bfloat16 Vh[32 * 72], Vl[32 * 72];
    __shared__ float eqs[64], eks[32];
    const int tile = 15 - blockIdx.x, h = blockIdx.y, c = blockIdx.z;
    const int tid = threadIdx.x, lane = tid & 31, w = tid >> 5;
    const int l0 = tile * 64;

    {
        const size_t qb = ((size_t)h * TT + c * LL + l0) * DD;
#pragma unroll
        for (int idx = tid; idx < 512; idx += 128) {
            const int l = idx >> 3, u = (idx & 7) * 8;
            *(uint4*)&Qh[l * 72 + u] = *(const uint4*)&Qsh_g[qb + l * 64 + u];
            *(uint4*)&Ql[l * 72 + u] = *(const uint4*)&Qsl_g[qb + l * 64 + u];
        }
    }
    if (tid < 64) eqs[tid] = __expf(g_buf[(c * HH + h) * LL + l0 + tid]);

    const int m0w = w * 16;
    const int r0 = m0w + (lane >> 2);
    const uint32_t QhB = smem_u32(Qh), QlB = smem_u32(Ql);
    const uint32_t KhB = smem_u32(Kh), KlB = smem_u32(Kl);
    const uint32_t VhB = smem_u32(Vh), VlB = smem_u32(Vl);
    const uint32_t aoffQ = ((m0w + (lane & 15)) * 72 + (lane >> 4) * 8) * 2;
    const uint32_t boff = ((lane & 15) * 72 + (lane >> 4) * 8) * 2;

    float oacc[8][4];
#pragma unroll
    for (int i = 0; i < 8; i++)
#pragma unroll
        for (int j = 0; j < 4; j++) oacc[i][j] = 0.f;
    float rs0 = 0.f, rs1 = 0.f;

    const int nst = 2 * (tile + 1);
    for (int st = 0; st < nst; st++) {
        __syncthreads();
        {
            const size_t kb = ((size_t)h * TT + c * LL + st * 32) * DD;
#pragma unroll
            for (int idx = tid; idx < 256; idx += 128) {
                const int l = idx >> 3, u = (idx & 7) * 8;
                const int so = l * 72 + u;
                const size_t go = kb + l * 64 + u;
                const uint4 a = *(const uint4*)&Ksh_g[go];
                const uint4 b = *(const uint4*)&Ksl_g[go];
                const uint4 cc2 = *(const uint4*)&Vsh_g[go];
                const uint4 d = *(const uint4*)&Vsl_g[go];
                *(uint4*)&Kh[so] = a;
                *(uint4*)&Kl[so] = b;
                *(uint4*)&Vh[so] = cc2;
                *(uint4*)&Vl[so] = d;
            }
        }
        if (tid < 32) eks[tid] = __expf(-g_buf[(c * HH + h) * LL + st * 32 + tid]);
        __syncthreads();

        float sc[4][4];
#pragma unroll
        for (int i = 0; i < 4; i++)
#pragma unroll
            for (int j = 0; j < 4; j++) sc[i][j] = 0.f;
#pragma unroll
        for (int kd = 0; kd < 4; kd++) {
            uint32_t ah[4], al[4];
            ldsm4(ah, QhB + aoffQ + kd * 32);
            ldsm4(al, QlB + aoffQ + kd * 32);
#pragma unroll
            for (int ng = 0; ng < 2; ng++) {
                uint32_t kh4[4], kl4[4];
                const uint32_t rb = (uint32_t)(ng * 16 * 72 * 2) + boff + kd * 32;
                ldsm4(kh4, KhB + rb);
                ldsm4(kl4, KlB + rb);
                mma16816s(sc[ng * 2],     ah, kh4[0], kh4[2]);
                mma16816s(sc[ng * 2],     ah, kl4[0], kl4[2]);
                mma16816s(sc[ng * 2],     al, kh4[0], kh4[2]);
                mma16816s(sc[ng * 2 + 1], ah, kh4[1], kh4[3]);
                mma16816s(sc[ng * 2 + 1], ah, kl4[1], kl4[3]);
                mma16816s(sc[ng * 2 + 1], al, kh4[1], kh4[3]);
            }
        }

        const float eq0 = eqs[r0], eq1 = eqs[r0 + 8];
        const int soff = st * 32 - l0;
        uint32_t wah[2][4], wal[2][4];
#pragma unroll
        for (int nt = 0; nt < 4; nt++) {
            const int sA = nt * 8 + 2 * (lane & 3);
            const float ekA = eks[sA], ekB = eks[sA + 1];
            float w00 = eq0 * ekA * sc[nt][0] * sc[nt][0];
            float w01 = eq0 * ekB * sc[nt][1] * sc[nt][1];
            float w10 = eq1 * ekA * sc[nt][2] * sc[nt][2];
            float w11 = eq1 * ekB * sc[nt][3] * sc[nt][3];
            if (soff >= 0) {
                if (r0 < soff + sA) w00 = 0.f;
                if (r0 < soff + sA + 1) w01 = 0.f;
                if (r0 + 8 < soff + sA) w10 = 0.f;
                if (r0 + 8 < soff + sA + 1) w11 = 0.f;
            }
            rs0 += w00 + w01;
            rs1 += w10 + w11;
            const int ks = nt >> 1, hf2 = (nt & 1) * 2;
            split2(w00, w01, wah[ks][hf2], wal[ks][hf2]);
            split2(w10, w11, wah[ks][hf2 + 1], wal[ks][hf2 + 1]);
        }

#pragma unroll
        for (int ks = 0; ks < 2; ks++) {
#pragma unroll
            for (int nv = 0; nv < 4; nv++) {
                uint32_t vh4[4], vl4[4];
                const uint32_t bo = boff + (uint32_t)(ks * 16 * 72 * 2) + nv * 32;
                ldsm4t(vh4, VhB + bo);
                ldsm4t(vl4, VlB + bo);
                mma16816s(oacc[nv * 2],     wah[ks], vh4[0], vh4[1]);
                mma16816s(oacc[nv * 2],     wah[ks], vl4[0], vl4[1]);
                mma16816s(oacc[nv * 2],     wal[ks], vh4[0], vh4[1]);
                mma16816s(oacc[nv * 2 + 1], wah[ks], vh4[2], vh4[3]);
                mma16816s(oacc[nv * 2 + 1], wah[ks], vl4[2], vl4[3]);
                mma16816s(oacc[nv * 2 + 1], wal[ks], vh4[2], vh4[3]);
            }
        }
    }

    rs0 += __shfl_xor_sync(0xffffffffu, rs0, 1);
    rs0 += __shfl_xor_sync(0xffffffffu, rs0, 2);
    rs1 += __shfl_xor_sync(0xffffffffu, rs1, 1);
    rs1 += __shfl_xor_sync(0xffffffffu, rs1, 2);
    const int t0 = c * LL + l0 + r0, t1 = t0 + 8;
    if ((lane & 3) == 0) {
        row_buf[t0 * HH + h] = rs0;
        row_buf[t1 * HH + h] = rs1;
    }
    float* O0 = &out[((size_t)t0 * HH + h) * DD];
    float* O1 = &out[((size_t)t1 * HH + h) * DD];
#pragma unroll
    for (int nt = 0; nt < 8; nt++) {
        const int c2 = nt * 8 + 2 * (lane & 3);
        *(float2*)&O0[c2] = make_float2(oacc[nt][0], oacc[nt][1]);
        *(float2*)&O1[c2] = make_float2(oacc[nt][2], oacc[nt][3]);
    }
}

// ---------------------------------------------------------------------------
// K2: pz via bf16-split mma.sync — R7 shape (256 thr, 8 warps x 16p x 64v)
// with packed uint2 A-build. grid (17, H, 3).
// ---------------------------------------------------------------------------
__global__ void __launch_bounds__(256) pz_tc_kernel(const float* __restrict__ k) {
    __shared__ float Ks[32 * 67];                           // [l][d] fp32
    __shared__ __align__(16) __nv_bfloat16 Bh[32 * 72];     // V split hi [l][v]
    __shared__ __align__(16) __nv_bfloat16 Bl[32 * 72];
    __shared__ __align__(16) __nv_bfloat16 Ah[128 * 40];    // A split hi [p][l]
    __shared__ __align__(16) __nv_bfloat16 Al[128 * 40];
    __shared__ float wl[32];
    const int bt = blockIdx.x, h = blockIdx.y, c = blockIdx.z;
    const int tid = threadIdx.x, lane = tid & 31, w = tid >> 5;
    const int p0 = bt * 128;
    const short2 de = lut_de[p0 + (tid >> 1)];
    const float m0 = (p0 + (tid >> 1) >= PREAL) ? 0.f
                     : ((de.x == de.y) ? 1.f : 2.f);
    const int lh = (tid & 1) * 16;
    const int pr = tid >> 1;
    const int kx = de.x, ky = de.y;
    const float gend = g_buf[(c * HH + h) * LL + LL - 1];
    float zacc = 0.f;

    float acc[8][4];
#pragma unroll
    for (int i = 0; i < 8; i++)
#pragma unroll
        for (int j = 0; j < 4; j++) acc[i][j] = 0.f;

    const uint32_t AhB = smem_u32(Ah), AlB = smem_u32(Al);
    const uint32_t BhB = smem_u32(Bh), BlB = smem_u32(Bl);
    const int m0w = w * 16;
    const uint32_t aoff = ((m0w + (lane & 15)) * 40 + (lane >> 4) * 8) * 2;
    const uint32_t boff = ((lane & 15) * 72 + (lane >> 4) * 8) * 2;

    for (int lt = 0; lt < 32; lt++) {
        const int l0g = lt * 32;
        __syncthreads();
        {   // stage presplit V + fp32 K
            const size_t vb = ((size_t)h * TT + c * LL + l0g) * DD;
#pragma unroll
            for (int idx = tid; idx < 256; idx += 256) {
                const int l = idx >> 3, u = (idx & 7) * 8;
                const int so = l * 72 + u;
                const size_t go = vb + l * 64 + u;
                *(uint4*)&Bh[so] = *(const uint4*)&Vsh_g[go];
                *(uint4*)&Bl[so] = *(const uint4*)&Vsl_g[go];
            }
#pragma unroll
            for (int idx = tid; idx < 512; idx += 256) {
                const int l = idx >> 4, d4 = (idx & 15) << 2;
                const size_t gb = ((size_t)(c * LL + l0g + l) * HH + h) * DD + d4;
                const float4 kv = *(const float4*)&k[gb];
                Ks[l * 67 + d4 + 0] = kv.x;
                Ks[l * 67 + d4 + 1] = kv.y;
                Ks[l * 67 + d4 + 2] = kv.z;
                Ks[l * 67 + d4 + 3] = kv.w;
            }
        }
        if (tid < 32)
            wl[tid] = __expf(gend - g_buf[(c * HH + h) * LL + l0g + tid]);
        __syncthreads();
        // A build: 2 threads per p-row, 16 l each; packed uint2 stores
#pragma unroll
        for (int j = 0; j < 16; j += 4) {
            const int l = lh + j;
            const float a0 = m0 * wl[l + 0] * Ks[(l + 0) * 67 + kx] * Ks[(l + 0) * 67 + ky];
            const float a1 = m0 * wl[l + 1] * Ks[(l + 1) * 67 + kx] * Ks[(l + 1) * 67 + ky];
            const float a2 = m0 * wl[l + 2] * Ks[(l + 2) * 67 + kx] * Ks[(l + 2) * 67 + ky];
            const float a3 = m0 * wl[l + 3] * Ks[(l + 3) * 67 + kx] * Ks[(l + 3) * 67 + ky];
            zacc += (a0 + a1) + (a2 + a3);
            uint32_t h0, lo0, h1, lo1;
            split2(a0, a1, h0, lo0);
            split2(a2, a3, h1, lo1);
            *(uint2*)&Ah[pr * 40 + l] = make_uint2(h0, h1);
            *(uint2*)&Al[pr * 40 + l] = make_uint2(lo0, lo1);
        }
        __syncthreads();
#pragma unroll
        for (int ks = 0; ks < 2; ks++) {
            uint32_t ah[4], al[4];
            ldsm4(ah, AhB + aoff + ks * 32);
            ldsm4(al, AlB + aoff + ks * 32);
#pragma unroll
            for (int nt2 = 0; nt2 < 4; nt2++) {
                uint32_t bh[4], bl[4];
                const uint32_t bo = boff + ks * (16 * 72 * 2) + nt2 * 32;
                ldsm4t(bh, BhB + bo);
                ldsm4t(bl, BlB + bo);
                mma16816(acc[2 * nt2],     ah, bh);
                mma16816(acc[2 * nt2],     ah, bl);
                mma16816(acc[2 * nt2],     al, bh);
                mma16816(acc[2 * nt2 + 1], ah, bh + 2);
                mma16816(acc[2 * nt2 + 1], ah, bl + 2);
                mma16816(acc[2 * nt2 + 1], al, bh + 2);
            }
        }
    }

    const float zo = zacc + __shfl_xor_sync(0xffffffffu, zacc, 1);
    const size_t pb = (size_t)(c * HH + h) * PTOT + p0;
    if (!(tid & 1)) z_buf[pb + pr] = zo;

    const int r0 = m0w + (lane >> 2);
    float* P0 = &P_buf[(pb + r0) * 64];
    float* P1 = &P_buf[(pb + r0 + 8) * 64];
#pragma unroll
    for (int nt = 0; nt < 8; nt++) {
        const int c2 = nt * 8 + 2 * (lane & 3);
        *(float2*)&P0[c2] = make_float2(acc[nt][0], acc[nt][1]);
        *(float2*)&P1[c2] = make_float2(acc[nt][2], acc[nt][3]);
    }
}

// ---------------------------------------------------------------------------
// K2b: prefix-state combine; emits SPLIT bf16 prefix states directly.
// ---------------------------------------------------------------------------
__global__ void combineP_kernel() {
    const int perh = PTOT * 16;
    int idx = blockIdx.x * 256 + threadIdx.x;
    if (idx >= HH * perh) return;
    int h = idx / perh, r = idx % perh;
    const float gt1 = __expf(g_buf[(1 * HH + h) * LL + LL - 1]);
    const float gt2 = __expf(g_buf[(2 * HH + h) * LL + LL - 1]);
    const float4* P = (const float4*)P_buf;
    const size_t o0 = (size_t)(0 * HH + h) * perh + r;
    const size_t o1 = (size_t)(1 * HH + h) * perh + r;
    const size_t o2 = (size_t)(2 * HH + h) * perh + r;
    const float4 p0 = P[o0], p1 = P[o1], p2 = P[o2];
    float4 s1 = p0;
    float4 s2 = make_float4(gt1 * s1.x + p1.x, gt1 * s1.y + p1.y,
                            gt1 * s1.z + p1.z, gt1 * s1.w + p1.w);
    float4 s3 = make_float4(gt2 * s2.x + p2.x, gt2 * s2.y + p2.y,
                            gt2 * s2.z + p2.z, gt2 * s2.w + p2.w);
    uint32_t a0, b0, a1, b1;
    split2(s1.x, s1.y, a0, b0); split2(s1.z, s1.w, a1, b1);
    *(uint2*)&Sh_g[o0 * 4] = make_uint2(a0, a1);
    *(uint2*)&Sl_g[o0 * 4] = make_uint2(b0, b1);
    split2(s2.x, s2.y, a0, b0); split2(s2.z, s2.w, a1, b1);
    *(uint2*)&Sh_g[o1 * 4] = make_uint2(a0, a1);
    *(uint2*)&Sl_g[o1 * 4] = make_uint2(b0, b1);
    split2(s3.x, s3.y, a0, b0); split2(s3.z, s3.w, a1, b1);
    *(uint2*)&Sh_g[o2 * 4] = make_uint2(a0, a1);
    *(uint2*)&Sl_g[o2 * 4] = make_uint2(b0, b1);
}

__global__ void combineZ_kernel() {
    int idx = blockIdx.x * 256 + threadIdx.x;
    if (idx >= HH * PTOT) return;
    int h = idx / PTOT, r = idx % PTOT;
    const float gt1 = __expf(g_buf[(1 * HH + h) * LL + LL - 1]);
    const float gt2 = __expf(g_buf[(2 * HH + h) * LL + LL - 1]);
    const float p0 = z_buf[(0 * HH + h) * PTOT + r];
    const float p1 = z_buf[(1 * HH + h) * PTOT + r];
    const float p2 = z_buf[(2 * HH + h) * PTOT + r];
    float s1 = p0;
    float s2 = gt1 * s1 + p1;
    float s3 = gt2 * s2 + p2;
    zs_buf[(0 * HH + h) * PTOT + r] = s1;
    zs_buf[(1 * HH + h) * PTOT + r] = s2;
    zs_buf[(2 * HH + h) * PTOT + r] = s3;
}

// ---------------------------------------------------------------------------
// K3: inter via bf16-split mma.sync + finalize (R8 version, kept).
// ---------------------------------------------------------------------------
__global__ void __launch_bounds__(128) inter_tc_kernel(
    const float* __restrict__ q, float* __restrict__ out) {
    const int bx = blockIdx.x, h = blockIdx.y, c = blockIdx.z;
    const int tid = threadIdx.x, lane = tid & 31, w = tid >> 5;
    const int l0 = bx * 64;

    if (c == 0) {
        for (int idx = tid; idx < 1024; idx += 128) {
            int l = idx >> 4, v4 = (idx & 15) << 2;
            const int t_ = l0 + l;
            const float inv = 1.f / fmaxf(row_buf[t_ * HH + h], EPSV);
            float4 ov = *(float4*)&out[((size_t)t_ * HH + h) * DD + v4];
            ov.x *= inv; ov.y *= inv; ov.z *= inv; ov.w *= inv;
            *(float4*)&out[((size_t)t_ * HH + h) * DD + v4] = ov;
        }
        return;
    }

    __shared__ float Qs[64 * 65];
    __shared__ __align__(16) __nv_bfloat16 Ah[64 * 40];
    __shared__ __align__(16) __nv_bfloat16 Al[64 * 40];
    __shared__ __align__(16) __nv_bfloat16 Bh[32 * 72];
    __shared__ __align__(16) __nv_bfloat16 Bl[32 * 72];
    __shared__ float zv[32];
    __shared__ short2 lutS[32];
    __shared__ float denp[128];
    __shared__ float denl[64];

    for (int idx = tid; idx < 1024; idx += 128) {
        int l = idx >> 4, d4 = (idx & 15) << 2;
        float4 qv = *(const float4*)&q[((size_t)(c * LL + l0 + l) * HH + h) * DD + d4];
        Qs[l * 65 + d4 + 0] = qv.x * QSCALE;
        Qs[l * 65 + d4 + 1] = qv.y * QSCALE;
        Qs[l * 65 + d4 + 2] = qv.z * QSCALE;
        Qs[l * 65 + d4 + 3] = qv.w * QSCALE;
    }
    const int lrow = tid >> 1, ph = (tid & 1) * 16;
    const float qdl = __expf(g_buf[(c * HH + h) * LL + l0 + lrow]);
    float dacc = 0.f;

    const int mf = w & 1, nh = w >> 1;
    float acc[2][4][4];
#pragma unroll
    for (int f = 0; f < 2; f++)
#pragma unroll
        for (int i = 0; i < 4; i++)
#pragma unroll
            for (int j = 0; j < 4; j++) acc[f][i][j] = 0.f;

    const size_t Sbase = (size_t)((c - 1) * HH + h) * PTOT * DD;
    const float* zp = &zs_buf[((c - 1) * HH + h) * PTOT];
    const uint32_t AhB = smem_u32(Ah), AlB = smem_u32(Al);
    const uint32_t BhB = smem_u32(Bh), BlB = smem_u32(Bl);
    uint32_t aoff[2];
    aoff[0] = ((mf * 32 + (lane & 15)) * 40 + (lane >> 4) * 8) * 2;
    aoff[1] = aoff[0] + 16 * 40 * 2;
    const uint32_t boff = ((lane & 15) * 72 + (lane >> 4) * 8) * 2;

    for (int pt = 0; pt < PTOT / 32; pt++) {
        const int p0 = pt * 32;
        __syncthreads();
        {
            const size_t sb2 = Sbase + (size_t)p0 * 64;
#pragma unroll
            for (int idx = tid; idx < 256; idx += 128) {
                const int pp = idx >> 3, u = (idx & 7) * 8;
                const int so = pp * 72 + u;
                const size_t go = sb2 + pp * 64 + u;
                *(uint4*)&Bh[so] = *(const uint4*)&Sh_g[go];
                *(uint4*)&Bl[so] = *(const uint4*)&Sl_g[go];
            }
        }
        if (tid < 32) {
            zv[tid] = zp[p0 + tid];
            lutS[tid] = lut_de[p0 + tid];
        }
        __syncthreads();
#pragma unroll
        for (int j = 0; j < 16; j++) {
            const int pp = ph + j;
            const short2 de = lutS[pp];
            const float a = qdl * Qs[lrow * 65 + de.x] * Qs[lrow * 65 + de.y];
            dacc += a * zv[pp];
            split_st(Ah, Al, lrow * 40 + pp, a);
        }
        __syncthreads();
#pragma unroll
        for (int ks = 0; ks < 2; ks++) {
            uint32_t ah0[4], al0[4], ah1[4], al1[4];
            ldsm4(ah0, AhB + aoff[0] + ks * 32);
            ldsm4(al0, AlB + aoff[0] + ks * 32);
            ldsm4(ah1, AhB + aoff[1] + ks * 32);
            ldsm4(al1, AlB + aoff[1] + ks * 32);
#pragma unroll
            for (int t2 = 0; t2 < 2; t2++) {
                const int nt2 = nh * 2 + t2;
                uint32_t bh[4], bl[4];
                const uint32_t bo = boff + ks * (16 * 72 * 2) + nt2 * 32;
                ldsm4t(bh, BhB + bo);
                ldsm4t(bl, BlB + bo);
                mma16816(acc[0][2 * t2],     ah0, bh);
                mma16816(acc[0][2 * t2],     ah0, bl);
                mma16816(acc[0][2 * t2],     al0, bh);
                mma16816(acc[0][2 * t2 + 1], ah0, bh + 2);
                mma16816(acc[0][2 * t2 + 1], ah0, bl + 2);
                mma16816(acc[0][2 * t2 + 1], al0, bh + 2);
                mma16816(acc[1][2 * t2],     ah1, bh);
                mma16816(acc[1][2 * t2],     ah1, bl);
                mma16816(acc[1][2 * t2],     al1, bh);
                mma16816(acc[1][2 * t2 + 1], ah1, bh + 2);
                mma16816(acc[1][2 * t2 + 1], ah1, bl + 2);
                mma16816(acc[1][2 * t2 + 1], al1, bh + 2);
            }
        }
    }

    denp[tid] = dacc;
    __syncthreads();
    if (tid < 64) denl[tid] = denp[2 * tid] + denp[2 * tid + 1];
    __syncthreads();

#pragma unroll
    for (int f = 0; f < 2; f++) {
        const int rl = mf * 32 + f * 16 + (lane >> 2);
        const int t0 = c * LL + l0 + rl, t1 = t0 + 8;
        const float inv0 = 1.f / fmaxf(row_buf[t0 * HH + h] + denl[rl], EPSV);
        const float inv1 = 1.f / fmaxf(row_buf[t1 * HH + h] + denl[rl + 8], EPSV);
        float* O0 = &out[((size_t)t0 * HH + h) * DD];
        float* O1 = &out[((size_t)t1 * HH + h) * DD];
#pragma unroll
        for (int j = 0; j < 4; j++) {
            const int c2 = nh * 32 + j * 8 + 2 * (lane & 3);
            float2 o0 = *(float2*)&O0[c2];
            o0.x = (o0.x + acc[f][j][0]) * inv0;
            o0.y = (o0.y + acc[f][j][1]) * inv0;
            *(float2*)&O0[c2] = o0;
            float2 o1 = *(float2*)&O1[c2];
            o1.x = (o1.x + acc[f][j][2]) * inv1;
            o1.y = (o1.y + acc[f][j][3]) * inv1;
            *(float2*)&O1[c2] = o1;
        }
    }
}

extern "C" void kernel_launch(void* const* d_in, const int* in_sizes, int n_in,
                              void* d_out, int out_size) {
    const float* q = (const float*)d_in[0];
    const float* k = (const float*)d_in[1];
    const float* v = (const float*)d_in[2];
    const float* lg = (const float*)d_in[3];
    float* out = (float*)d_out;

    init_kernel<<<CC * HH + 1, 256>>>(lg);

    dim3 gs(TT / 64, HH);
    split_kernel<<<gs, 256>>>(q, k, v);

    dim3 gt(16, HH, CC);
    intra_tc_kernel<<<gt, 128>>>(out);

    dim3 gp(PTOT / 128, HH, CC - 1);
    pz_tc_kernel<<<gp, 256>>>(k);

    combineP_kernel<<<(HH * PTOT * 16 + 255) / 256, 256>>>();
    combineZ_kernel<<<(HH * PTOT + 255) / 256, 256>>>();

    dim3 gi(16, HH, CC);
    inter_tc_kernel<<<gi, 128>>>(q, out);
}

// round 12
// speedup vs baseline: 1.0279x; 1.0279x over previous
#include <cuda_runtime.h>
#include <cuda_bf16.h>
#include <cstdint>

#define CC 4
#define LL 1024
#define HH 8
#define DD 64
#define TT (CC*LL)
#define QSCALE 0.125f
#define EPSV 1e-6f
#define PTOT 2176   // 2080 unique (d<=e) pairs + 96 pad
#define PREAL 2080

// Scratch (static __device__ — no allocation allowed)
__device__ float g_buf[CC*HH*LL];
__device__ float P_buf[(size_t)3*HH*PTOT*DD];
__device__ float z_buf[3*HH*PTOT];
__device__ float zs_buf[3*HH*PTOT];
__device__ float row_buf[TT*HH];
__device__ short2 lut_de[PTOT];
__device__ __nv_bfloat16 Qsh_g[(size_t)TT*HH*DD], Qsl_g[(size_t)TT*HH*DD];
__device__ __nv_bfloat16 Ksh_g[(size_t)TT*HH*DD], Ksl_g[(size_t)TT*HH*DD];
__device__ __nv_bfloat16 Vsh_g[(size_t)TT*HH*DD], Vsl_g[(size_t)TT*HH*DD];
__device__ __nv_bfloat16 Sh_g[(size_t)3*HH*PTOT*DD], Sl_g[(size_t)3*HH*PTOT*DD];

// ---------------------------------------------------------------------------
// mma.sync helpers
// ---------------------------------------------------------------------------
__device__ __forceinline__ uint32_t smem_u32(const void* p) {
    uint32_t a;
    asm("{ .reg .u64 t; cvta.to.shared.u64 t, %1; cvt.u32.u64 %0, t; }"
        : "=r"(a) : "l"(p));
    return a;
}
__device__ __forceinline__ void ldsm4(uint32_t* r, uint32_t a) {
    asm volatile("ldmatrix.sync.aligned.m8n8.x4.shared.b16 {%0,%1,%2,%3}, [%4];"
        : "=r"(r[0]), "=r"(r[1]), "=r"(r[2]), "=r"(r[3]) : "r"(a));
}
__device__ __forceinline__ void ldsm4t(uint32_t* r, uint32_t a) {
    asm volatile("ldmatrix.sync.aligned.m8n8.x4.trans.shared.b16 {%0,%1,%2,%3}, [%4];"
        : "=r"(r[0]), "=r"(r[1]), "=r"(r[2]), "=r"(r[3]) : "r"(a));
}
__device__ __forceinline__ void mma16816(float* d, const uint32_t* a, const uint32_t* b) {
    asm volatile("mma.sync.aligned.m16n8k16.row.col.f32.bf16.bf16.f32 "
        "{%0,%1,%2,%3}, {%4,%5,%6,%7}, {%8,%9}, {%0,%1,%2,%3};"
        : "+f"(d[0]), "+f"(d[1]), "+f"(d[2]), "+f"(d[3])
        : "r"(a[0]), "r"(a[1]), "r"(a[2]), "r"(a[3]), "r"(b[0]), "r"(b[1]));
}
__device__ __forceinline__ void mma16816s(float* d, const uint32_t* a,
                                          uint32_t b0, uint32_t b1) {
    asm volatile("mma.sync.aligned.m16n8k16.row.col.f32.bf16.bf16.f32 "
        "{%0,%1,%2,%3}, {%4,%5,%6,%7}, {%8,%9}, {%0,%1,%2,%3};"
        : "+f"(d[0]), "+f"(d[1]), "+f"(d[2]), "+f"(d[3])
        : "r"(a[0]), "r"(a[1]), "r"(a[2]), "r"(a[3]), "r"(b0), "r"(b1));
}
__device__ __forceinline__ void split_st(__nv_bfloat16* hb, __nv_bfloat16* lb,
                                         int idx, float a) {
    __nv_bfloat16 hv = __float2bfloat16(a);
    hb[idx] = hv;
    lb[idx] = __float2bfloat16(a - __bfloat162float(hv));
}
__device__ __forceinline__ void split2(float x, float y, uint32_t& hi, uint32_t& lo) {
    __nv_bfloat16 xh = __float2bfloat16(x), yh = __float2bfloat16(y);
    __nv_bfloat16 xl = __float2bfloat16(x - __bfloat162float(xh));
    __nv_bfloat16 yl = __float2bfloat16(y - __bfloat162float(yh));
    hi = (uint32_t)*(uint16_t*)&xh | ((uint32_t)*(uint16_t*)&yh << 16);
    lo = (uint32_t)*(uint16_t*)&xl | ((uint32_t)*(uint16_t*)&yl << 16);
}

// ---------------------------------------------------------------------------
// K0a: pre-split Q*scale, K, V into global bf16 hi/lo, [h][t][d] layout.
// ---------------------------------------------------------------------------
__global__ void split_kernel(const float* __restrict__ q,
                             const float* __restrict__ k,
                             const float* __restrict__ v) {
    const int t0 = blockIdx.x * 64, h = blockIdx.y;
    for (int idx = threadIdx.x; idx < 1024; idx += 256) {
        const int l = idx >> 4, d4 = (idx & 15) << 2;
        const int t = t0 + l;
        const size_t gi = ((size_t)t * HH + h) * DD + d4;
        const size_t oo = ((size_t)h * TT + t) * DD + d4;
        uint32_t a0, b0, a1, b1;
        const float4 qv = *(const float4*)&q[gi];
        split2(qv.x * QSCALE, qv.y * QSCALE, a0, b0);
        split2(qv.z * QSCALE, qv.w * QSCALE, a1, b1);
        *(uint2*)&Qsh_g[oo] = make_uint2(a0, a1);
        *(uint2*)&Qsl_g[oo] = make_uint2(b0, b1);
        const float4 kv = *(const float4*)&k[gi];
        split2(kv.x, kv.y, a0, b0);
        split2(kv.z, kv.w, a1, b1);
        *(uint2*)&Ksh_g[oo] = make_uint2(a0, a1);
        *(uint2*)&Ksl_g[oo] = make_uint2(b0, b1);
        const float4 vv = *(const float4*)&v[gi];
        split2(vv.x, vv.y, a0, b0);
        split2(vv.z, vv.w, a1, b1);
        *(uint2*)&Vsh_g[oo] = make_uint2(a0, a1);
        *(uint2*)&Vsl_g[oo] = make_uint2(b0, b1);
    }
}

// ---------------------------------------------------------------------------
// K0b: cumsum per (c,h) + pair-LUT build (last block)
// ---------------------------------------------------------------------------
__global__ void init_kernel(const float* __restrict__ lg) {
    if (blockIdx.x == CC * HH) {
        for (int p = threadIdx.x; p < PTOT; p += 256) {
            short d = 0, e = 0;
            if (p < PREAL) {
                int off = 0, dd = 0;
                while (off + (DD - dd) <= p) { off += DD - dd; dd++; }
                d = (short)dd; e = (short)(dd + (p - off));
            }
            lut_de[p] = make_short2(d, e);
        }
        return;
    }
    int c = blockIdx.x / HH, h = blockIdx.x % HH;
    int t = threadIdx.x;
    float vloc[4];
    float s = 0.f;
#pragma unroll
    for (int i = 0; i < 4; i++) {
        int l = t * 4 + i;
        s += lg[(c * LL + l) * HH + h];
        vloc[i] = s;
    }
    float tot = s;
#pragma unroll
    for (int off = 1; off < 32; off <<= 1) {
        float n = __shfl_up_sync(0xffffffffu, tot, off);
        if ((t & 31) >= off) tot += n;
    }
    __shared__ float wsum[8];
    __shared__ float woff[8];
    if ((t & 31) == 31) wsum[t >> 5] = tot;
    __syncthreads();
    if (t == 0) {
        float a = 0.f;
        for (int w = 0; w < 8; w++) { woff[w] = a; a += wsum[w]; }
    }
    __syncthreads();
    float ex = woff[t >> 5] + (tot - s);
#pragma unroll
    for (int i = 0; i < 4; i++)
        g_buf[(c * HH + h) * LL + t * 4 + i] = ex + vloc[i];
}

// ---------------------------------------------------------------------------
// K1: intra-chunk causal attention via bf16-split mma.sync.
// Heavy tiles launch first (tile = 15 - blockIdx.x) for wave packing.
// ---------------------------------------------------------------------------
__global__ void __launch_bounds__(128) intra_tc_kernel(float* __restrict__ out) {
    __shared__ __align__(16) __nv_bfloat16 Qh[64 * 72], Ql[64 * 72];
    __shared__ __align__(16) __nv_bfloat16 Kh[32 * 72], Kl[32 * 72];
    __shared__ __align__(16) __nv_bfloat16 Vh[32 * 72], Vl[32 * 72];
    __shared__ float eqs[64], eks[32];
    const int tile = 15 - blockIdx.x, h = blockIdx.y, c = blockIdx.z;
    const int tid = threadIdx.x, lane = tid & 31, w = tid >> 5;
    const int l0 = tile * 64;

    {
        const size_t qb = ((size_t)h * TT + c * LL + l0) * DD;
#pragma unroll
        for (int idx = tid; idx < 512; idx += 128) {
            const int l = idx >> 3, u = (idx & 7) * 8;
            *(uint4*)&Qh[l * 72 + u] = *(const uint4*)&Qsh_g[qb + l * 64 + u];
            *(uint4*)&Ql[l * 72 + u] = *(const uint4*)&Qsl_g[qb + l * 64 + u];
        }
    }
    if (tid < 64) eqs[tid] = __expf(g_buf[(c * HH + h) * LL + l0 + tid]);

    const int m0w = w * 16;
    const int r0 = m0w + (lane >> 2);
    const uint32_t QhB = smem_u32(Qh), QlB = smem_u32(Ql);
    const uint32_t KhB = smem_u32(Kh), KlB = smem_u32(Kl);
    const uint32_t VhB = smem_u32(Vh), VlB = smem_u32(Vl);
    const uint32_t aoffQ = ((m0w + (lane & 15)) * 72 + (lane >> 4) * 8) * 2;
    const uint32_t boff = ((lane & 15) * 72 + (lane >> 4) * 8) * 2;

    float oacc[8][4];
#pragma unroll
    for (int i = 0; i < 8; i++)
#pragma unroll
        for (int j = 0; j < 4; j++) oacc[i][j] = 0.f;
    float rs0 = 0.f, rs1 = 0.f;

    const int nst = 2 * (tile + 1);
    for (int st = 0; st < nst; st++) {
        __syncthreads();
        {
            const size_t kb = ((size_t)h * TT + c * LL + st * 32) * DD;
#pragma unroll
            for (int idx = tid; idx < 256; idx += 128) {
                const int l = idx >> 3, u = (idx & 7) * 8;
                const int so = l * 72 + u;
                const size_t go = kb + l * 64 + u;
                const uint4 a = *(const uint4*)&Ksh_g[go];
                const uint4 b = *(const uint4*)&Ksl_g[go];
                const uint4 cc2 = *(const uint4*)&Vsh_g[go];
                const uint4 d = *(const uint4*)&Vsl_g[go];
                *(uint4*)&Kh[so] = a;
                *(uint4*)&Kl[so] = b;
                *(uint4*)&Vh[so] = cc2;
                *(uint4*)&Vl[so] = d;
            }
        }
        if (tid < 32) eks[tid] = __expf(-g_buf[(c * HH + h) * LL + st * 32 + tid]);
        __syncthreads();

        float sc[4][4];
#pragma unroll
        for (int i = 0; i < 4; i++)
#pragma unroll
            for (int j = 0; j < 4; j++) sc[i][j] = 0.f;
#pragma unroll
        for (int kd = 0; kd < 4; kd++) {
            uint32_t ah[4], al[4];
            ldsm4(ah, QhB + aoffQ + kd * 32);
            ldsm4(al, QlB + aoffQ + kd * 32);
#pragma unroll
            for (int ng = 0; ng < 2; ng++) {
                uint32_t kh4[4], kl4[4];
                const uint32_t rb = (uint32_t)(ng * 16 * 72 * 2) + boff + kd * 32;
                ldsm4(kh4, KhB + rb);
                ldsm4(kl4, KlB + rb);
                mma16816s(sc[ng * 2],     ah, kh4[0], kh4[2]);
                mma16816s(sc[ng * 2],     ah, kl4[0], kl4[2]);
                mma16816s(sc[ng * 2],     al, kh4[0], kh4[2]);
                mma16816s(sc[ng * 2 + 1], ah, kh4[1], kh4[3]);
                mma16816s(sc[ng * 2 + 1], ah, kl4[1], kl4[3]);
                mma16816s(sc[ng * 2 + 1], al, kh4[1], kh4[3]);
            }
        }

        const float eq0 = eqs[r0], eq1 = eqs[r0 + 8];
        const int soff = st * 32 - l0;
        uint32_t wah[2][4], wal[2][4];
#pragma unroll
        for (int nt = 0; nt < 4; nt++) {
            const int sA = nt * 8 + 2 * (lane & 3);
            const float ekA = eks[sA], ekB = eks[sA + 1];
            float w00 = eq0 * ekA * sc[nt][0] * sc[nt][0];
            float w01 = eq0 * ekB * sc[nt][1] * sc[nt][1];
            float w10 = eq1 * ekA * sc[nt][2] * sc[nt][2];
            float w11 = eq1 * ekB * sc[nt][3] * sc[nt][3];
            if (soff >= 0) {
                if (r0 < soff + sA) w00 = 0.f;
                if (r0 < soff + sA + 1) w01 = 0.f;
                if (r0 + 8 < soff + sA) w10 = 0.f;
                if (r0 + 8 < soff + sA + 1) w11 = 0.f;
            }
            rs0 += w00 + w01;
            rs1 += w10 + w11;
            const int ks = nt >> 1, hf2 = (nt & 1) * 2;
            split2(w00, w01, wah[ks][hf2], wal[ks][hf2]);
            split2(w10, w11, wah[ks][hf2 + 1], wal[ks][hf2 + 1]);
        }

#pragma unroll
        for (int ks = 0; ks < 2; ks++) {
#pragma unroll
            for (int nv = 0; nv < 4; nv++) {
                uint32_t vh4[4], vl4[4];
                const uint32_t bo = boff + (uint32_t)(ks * 16 * 72 * 2) + nv * 32;
                ldsm4t(vh4, VhB + bo);
                ldsm4t(vl4, VlB + bo);
                mma16816s(oacc[nv * 2],     wah[ks], vh4[0], vh4[1]);
                mma16816s(oacc[nv * 2],     wah[ks], vl4[0], vl4[1]);
                mma16816s(oacc[nv * 2],     wal[ks], vh4[0], vh4[1]);
                mma16816s(oacc[nv * 2 + 1], wah[ks], vh4[2], vh4[3]);
                mma16816s(oacc[nv * 2 + 1], wah[ks], vl4[2], vl4[3]);
                mma16816s(oacc[nv * 2 + 1], wal[ks], vh4[2], vh4[3]);
            }
        }
    }

    rs0 += __shfl_xor_sync(0xffffffffu, rs0, 1);
    rs0 += __shfl_xor_sync(0xffffffffu, rs0, 2);
    rs1 += __shfl_xor_sync(0xffffffffu, rs1, 1);
    rs1 += __shfl_xor_sync(0xffffffffu, rs1, 2);
    const int t0 = c * LL + l0 + r0, t1 = t0 + 8;
    if ((lane & 3) == 0) {
        row_buf[t0 * HH + h] = rs0;
        row_buf[t1 * HH + h] = rs1;
    }
    float* O0 = &out[((size_t)t0 * HH + h) * DD];
    float* O1 = &out[((size_t)t1 * HH + h) * DD];
#pragma unroll
    for (int nt = 0; nt < 8; nt++) {
        const int c2 = nt * 8 + 2 * (lane & 3);
        *(float2*)&O0[c2] = make_float2(oacc[nt][0], oacc[nt][1]);
        *(float2*)&O1[c2] = make_float2(oacc[nt][2], oacc[nt][3]);
    }
}

// ---------------------------------------------------------------------------
// K2: pz via bf16-split mma.sync — exact R7 shape (256 thr, 8 warps x 16p),
// scalar split_st A-build, occupancy pinned to 3 blocks/SM. grid (17, H, 3).
// ---------------------------------------------------------------------------
__global__ void __launch_bounds__(256, 3) pz_tc_kernel(const float* __restrict__ k) {
    __shared__ float Ks[32 * 67];                           // [l][d] fp32
    __shared__ __align__(16) __nv_bfloat16 Bh[32 * 72];     // V split hi [l][v]
    __shared__ __align__(16) __nv_bfloat16 Bl[32 * 72];
    __shared__ __align__(16) __nv_bfloat16 Ah[128 * 40];    // A split hi [p][l]
    __shared__ __align__(16) __nv_bfloat16 Al[128 * 40];
    __shared__ float wl[32];
    const int bt = blockIdx.x, h = blockIdx.y, c = blockIdx.z;
    const int tid = threadIdx.x, lane = tid & 31, w = tid >> 5;
    const int p0 = bt * 128;
    const short2 de = lut_de[p0 + (tid >> 1)];
    const float m0 = (p0 + (tid >> 1) >= PREAL) ? 0.f
                     : ((de.x == de.y) ? 1.f : 2.f);
    const int lh = (tid & 1) * 16;
    const int pr = tid >> 1;
    const float gend = g_buf[(c * HH + h) * LL + LL - 1];
    float zacc = 0.f;

    float acc[8][4];
#pragma unroll
    for (int i = 0; i < 8; i++)
#pragma unroll
        for (int j = 0; j < 4; j++) acc[i][j] = 0.f;

    const uint32_t AhB = smem_u32(Ah), AlB = smem_u32(Al);
    const uint32_t BhB = smem_u32(Bh), BlB = smem_u32(Bl);
    const int m0w = w * 16;
    const uint32_t aoff = ((m0w + (lane & 15)) * 40 + (lane >> 4) * 8) * 2;
    const uint32_t boff = ((lane & 15) * 72 + (lane >> 4) * 8) * 2;

    for (int lt = 0; lt < 32; lt++) {
        const int l0g = lt * 32;
        __syncthreads();
        {   // stage presplit V + fp32 K
            const size_t vb = ((size_t)h * TT + c * LL + l0g) * DD;
            for (int idx = tid; idx < 256; idx += 256) {
                const int l = idx >> 3, u = (idx & 7) * 8;
                const int so = l * 72 + u;
                const size_t go = vb + l * 64 + u;
                *(uint4*)&Bh[so] = *(const uint4*)&Vsh_g[go];
                *(uint4*)&Bl[so] = *(const uint4*)&Vsl_g[go];
            }
            for (int idx = tid; idx < 512; idx += 256) {
                const int l = idx >> 4, d4 = (idx & 15) << 2;
                const size_t gb = ((size_t)(c * LL + l0g + l) * HH + h) * DD + d4;
                const float4 kv = *(const float4*)&k[gb];
                Ks[l * 67 + d4 + 0] = kv.x;
                Ks[l * 67 + d4 + 1] = kv.y;
                Ks[l * 67 + d4 + 2] = kv.z;
                Ks[l * 67 + d4 + 3] = kv.w;
            }
        }
        if (tid < 32)
            wl[tid] = __expf(gend - g_buf[(c * HH + h) * LL + l0g + tid]);
        __syncthreads();
        // A build: 2 threads per p-row, 16 l each (scalar split stores)
#pragma unroll
        for (int j = 0; j < 16; j++) {
            const int l = lh + j;
            const float a = m0 * wl[l] * Ks[l * 67 + de.x] * Ks[l * 67 + de.y];
            zacc += a;
            split_st(Ah, Al, pr * 40 + l, a);
        }
        __syncthreads();
#pragma unroll
        for (int ks = 0; ks < 2; ks++) {
            uint32_t ah[4], al[4];
            ldsm4(ah, AhB + aoff + ks * 32);
            ldsm4(al, AlB + aoff + ks * 32);
#pragma unroll
            for (int nt2 = 0; nt2 < 4; nt2++) {
                uint32_t bh[4], bl[4];
                const uint32_t bo = boff + ks * (16 * 72 * 2) + nt2 * 32;
                ldsm4t(bh, BhB + bo);
                ldsm4t(bl, BlB + bo);
                mma16816(acc[2 * nt2],     ah, bh);
                mma16816(acc[2 * nt2],     ah, bl);
                mma16816(acc[2 * nt2],     al, bh);
                mma16816(acc[2 * nt2 + 1], ah, bh + 2);
                mma16816(acc[2 * nt2 + 1], ah, bl + 2);
                mma16816(acc[2 * nt2 + 1], al, bh + 2);
            }
        }
    }

    const float zo = zacc + __shfl_xor_sync(0xffffffffu, zacc, 1);
    const size_t pb = (size_t)(c * HH + h) * PTOT + p0;
    if (!(tid & 1)) z_buf[pb + pr] = zo;

    const int r0 = m0w + (lane >> 2);
    float* P0 = &P_buf[(pb + r0) * 64];
    float* P1 = &P_buf[(pb + r0 + 8) * 64];
#pragma unroll
    for (int nt = 0; nt < 8; nt++) {
        const int c2 = nt * 8 + 2 * (lane & 3);
        *(float2*)&P0[c2] = make_float2(acc[nt][0], acc[nt][1]);
        *(float2*)&P1[c2] = make_float2(acc[nt][2], acc[nt][3]);
    }
}

// ---------------------------------------------------------------------------
// K2b: prefix-state combine; emits SPLIT bf16 prefix states directly.
// ---------------------------------------------------------------------------
__global__ void combineP_kernel() {
    const int perh = PTOT * 16;
    int idx = blockIdx.x * 256 + threadIdx.x;
    if (idx >= HH * perh) return;
    int h = idx / perh, r = idx % perh;
    const float gt1 = __expf(g_buf[(1 * HH + h) * LL + LL - 1]);
    const float gt2 = __expf(g_buf[(2 * HH + h) * LL + LL - 1]);
    const float4* P = (const float4*)P_buf;
    const size_t o0 = (size_t)(0 * HH + h) * perh + r;
    const size_t o1 = (size_t)(1 * HH + h) * perh + r;
    const size_t o2 = (size_t)(2 * HH + h) * perh + r;
    const float4 p0 = P[o0], p1 = P[o1], p2 = P[o2];
    float4 s1 = p0;
    float4 s2 = make_float4(gt1 * s1.x + p1.x, gt1 * s1.y + p1.y,
                            gt1 * s1.z + p1.z, gt1 * s1.w + p1.w);
    float4 s3 = make_float4(gt2 * s2.x + p2.x, gt2 * s2.y + p2.y,
                            gt2 * s2.z + p2.z, gt2 * s2.w + p2.w);
    uint32_t a0, b0, a1, b1;
    split2(s1.x, s1.y, a0, b0); split2(s1.z, s1.w, a1, b1);
    *(uint2*)&Sh_g[o0 * 4] = make_uint2(a0, a1);
    *(uint2*)&Sl_g[o0 * 4] = make_uint2(b0, b1);
    split2(s2.x, s2.y, a0, b0); split2(s2.z, s2.w, a1, b1);
    *(uint2*)&Sh_g[o1 * 4] = make_uint2(a0, a1);
    *(uint2*)&Sl_g[o1 * 4] = make_uint2(b0, b1);
    split2(s3.x, s3.y, a0, b0); split2(s3.z, s3.w, a1, b1);
    *(uint2*)&Sh_g[o2 * 4] = make_uint2(a0, a1);
    *(uint2*)&Sl_g[o2 * 4] = make_uint2(b0, b1);
}

__global__ void combineZ_kernel() {
    int idx = blockIdx.x * 256 + threadIdx.x;
    if (idx >= HH * PTOT) return;
    int h = idx / PTOT, r = idx % PTOT;
    const float gt1 = __expf(g_buf[(1 * HH + h) * LL + LL - 1]);
    const float gt2 = __expf(g_buf[(2 * HH + h) * LL + LL - 1]);
    const float p0 = z_buf[(0 * HH + h) * PTOT + r];
    const float p1 = z_buf[(1 * HH + h) * PTOT + r];
    const float p2 = z_buf[(2 * HH + h) * PTOT + r];
    float s1 = p0;
    float s2 = gt1 * s1 + p1;
    float s3 = gt2 * s2 + p2;
    zs_buf[(0 * HH + h) * PTOT + r] = s1;
    zs_buf[(1 * HH + h) * PTOT + r] = s2;
    zs_buf[(2 * HH + h) * PTOT + r] = s3;
}

// ---------------------------------------------------------------------------
// K3: inter via bf16-split mma.sync + finalize (R8 version, kept).
// ---------------------------------------------------------------------------
__global__ void __launch_bounds__(128) inter_tc_kernel(
    const float* __restrict__ q, float* __restrict__ out) {
    const int bx = blockIdx.x, h = blockIdx.y, c = blockIdx.z;
    const int tid = threadIdx.x, lane = tid & 31, w = tid >> 5;
    const int l0 = bx * 64;

    if (c == 0) {
        for (int idx = tid; idx < 1024; idx += 128) {
            int l = idx >> 4, v4 = (idx & 15) << 2;
            const int t_ = l0 + l;
            const float inv = 1.f / fmaxf(row_buf[t_ * HH + h], EPSV);
            float4 ov = *(float4*)&out[((size_t)t_ * HH + h) * DD + v4];
            ov.x *= inv; ov.y *= inv; ov.z *= inv; ov.w *= inv;
            *(float4*)&out[((size_t)t_ * HH + h) * DD + v4] = ov;
        }
        return;
    }

    __shared__ float Qs[64 * 65];
    __shared__ __align__(16) __nv_bfloat16 Ah[64 * 40];
    __shared__ __align__(16) __nv_bfloat16 Al[64 * 40];
    __shared__ __align__(16) __nv_bfloat16 Bh[32 * 72];
    __shared__ __align__(16) __nv_bfloat16 Bl[32 * 72];
    __shared__ float zv[32];
    __shared__ short2 lutS[32];
    __shared__ float denp[128];
    __shared__ float denl[64];

    for (int idx = tid; idx < 1024; idx += 128) {
        int l = idx >> 4, d4 = (idx & 15) << 2;
        float4 qv = *(const float4*)&q[((size_t)(c * LL + l0 + l) * HH + h) * DD + d4];
        Qs[l * 65 + d4 + 0] = qv.x * QSCALE;
        Qs[l * 65 + d4 + 1] = qv.y * QSCALE;
        Qs[l * 65 + d4 + 2] = qv.z * QSCALE;
        Qs[l * 65 + d4 + 3] = qv.w * QSCALE;
    }
    const int lrow = tid >> 1, ph = (tid & 1) * 16;
    const float qdl = __expf(g_buf[(c * HH + h) * LL + l0 + lrow]);
    float dacc = 0.f;

    const int mf = w & 1, nh = w >> 1;
    float acc[2][4][4];
#pragma unroll
    for (int f = 0; f < 2; f++)
#pragma unroll
        for (int i = 0; i < 4; i++)
#pragma unroll
            for (int j = 0; j < 4; j++) acc[f][i][j] = 0.f;

    const size_t Sbase = (size_t)((c - 1) * HH + h) * PTOT * DD;
    const float* zp = &zs_buf[((c - 1) * HH + h) * PTOT];
    const uint32_t AhB = smem_u32(Ah), AlB = smem_u32(Al);
    const uint32_t BhB = smem_u32(Bh), BlB = smem_u32(Bl);
    uint32_t aoff[2];
    aoff[0] = ((mf * 32 + (lane & 15)) * 40 + (lane >> 4) * 8) * 2;
    aoff[1] = aoff[0] + 16 * 40 * 2;
    const uint32_t boff = ((lane & 15) * 72 + (lane >> 4) * 8) * 2;

    for (int pt = 0; pt < PTOT / 32; pt++) {
        const int p0 = pt * 32;
        __syncthreads();
        {
            const size_t sb2 = Sbase + (size_t)p0 * 64;
#pragma unroll
            for (int idx = tid; idx < 256; idx += 128) {
                const int pp = idx >> 3, u = (idx & 7) * 8;
                const int so = pp * 72 + u;
                const size_t go = sb2 + pp * 64 + u;
                *(uint4*)&Bh[so] = *(const uint4*)&Sh_g[go];
                *(uint4*)&Bl[so] = *(const uint4*)&Sl_g[go];
            }
        }
        if (tid < 32) {
            zv[tid] = zp[p0 + tid];
            lutS[tid] = lut_de[p0 + tid];
        }
        __syncthreads();
#pragma unroll
        for (int j = 0; j < 16; j++) {
            const int pp = ph + j;
            const short2 de = lutS[pp];
            const float a = qdl * Qs[lrow * 65 + de.x] * Qs[lrow * 65 + de.y];
            dacc += a * zv[pp];
            split_st(Ah, Al, lrow * 40 + pp, a);
        }
        __syncthreads();
#pragma unroll
        for (int ks = 0; ks < 2; ks++) {
            uint32_t ah0[4], al0[4], ah1[4], al1[4];
            ldsm4(ah0, AhB + aoff[0] + ks * 32);
            ldsm4(al0, AlB + aoff[0] + ks * 32);
            ldsm4(ah1, AhB + aoff[1] + ks * 32);
            ldsm4(al1, AlB + aoff[1] + ks * 32);
#pragma unroll
            for (int t2 = 0; t2 < 2; t2++) {
                const int nt2 = nh * 2 + t2;
                uint32_t bh[4], bl[4];
                const uint32_t bo = boff + ks * (16 * 72 * 2) + nt2 * 32;
                ldsm4t(bh, BhB + bo);
                ldsm4t(bl, BlB + bo);
                mma16816(acc[0][2 * t2],     ah0, bh);
                mma16816(acc[0][2 * t2],     ah0, bl);
                mma16816(acc[0][2 * t2],     al0, bh);
                mma16816(acc[0][2 * t2 + 1], ah0, bh + 2);
                mma16816(acc[0][2 * t2 + 1], ah0, bl + 2);
                mma16816(acc[0][2 * t2 + 1], al0, bh + 2);
                mma16816(acc[1][2 * t2],     ah1, bh);
                mma16816(acc[1][2 * t2],     ah1, bl);
                mma16816(acc[1][2 * t2],     al1, bh);
                mma16816(acc[1][2 * t2 + 1], ah1, bh + 2);
                mma16816(acc[1][2 * t2 + 1], ah1, bl + 2);
                mma16816(acc[1][2 * t2 + 1], al1, bh + 2);
            }
        }
    }

    denp[tid] = dacc;
    __syncthreads();
    if (tid < 64) denl[tid] = denp[2 * tid] + denp[2 * tid + 1];
    __syncthreads();

#pragma unroll
    for (int f = 0; f < 2; f++) {
        const int rl = mf * 32 + f * 16 + (lane >> 2);
        const int t0 = c * LL + l0 + rl, t1 = t0 + 8;
        const float inv0 = 1.f / fmaxf(row_buf[t0 * HH + h] + denl[rl], EPSV);
        const float inv1 = 1.f / fmaxf(row_buf[t1 * HH + h] + denl[rl + 8], EPSV);
        float* O0 = &out[((size_t)t0 * HH + h) * DD];
        float* O1 = &out[((size_t)t1 * HH + h) * DD];
#pragma unroll
        for (int j = 0; j < 4; j++) {
            const int c2 = nh * 32 + j * 8 + 2 * (lane & 3);
            float2 o0 = *(float2*)&O0[c2];
            o0.x = (o0.x + acc[f][j][0]) * inv0;
            o0.y = (o0.y + acc[f][j][1]) * inv0;
            *(float2*)&O0[c2] = o0;
            float2 o1 = *(float2*)&O1[c2];
            o1.x = (o1.x + acc[f][j][2]) * inv1;
            o1.y = (o1.y + acc[f][j][3]) * inv1;
            *(float2*)&O1[c2] = o1;
        }
    }
}

extern "C" void kernel_launch(void* const* d_in, const int* in_sizes, int n_in,
                              void* d_out, int out_size) {
    const float* q = (const float*)d_in[0];
    const float* k = (const float*)d_in[1];
    const float* v = (const float*)d_in[2];
    const float* lg = (const float*)d_in[3];
    float* out = (float*)d_out;

    init_kernel<<<CC * HH + 1, 256>>>(lg);

    dim3 gs(TT / 64, HH);
    split_kernel<<<gs, 256>>>(q, k, v);

    dim3 gt(16, HH, CC);
    intra_tc_kernel<<<gt, 128>>>(out);

    dim3 gp(PTOT / 128, HH, CC - 1);
    pz_tc_kernel<<<gp, 256>>>(k);

    combineP_kernel<<<(HH * PTOT * 16 + 255) / 256, 256>>>();
    combineZ_kernel<<<(HH * PTOT + 255) / 256, 256>>>();

    dim3 gi(16, HH, CC);
    inter_tc_kernel<<<gi, 128>>>(q, out);
}

// round 13
// speedup vs baseline: 1.0741x; 1.0449x over previous
#include <cuda_runtime.h>
#include <cuda_bf16.h>
#include <cstdint>

#define CC 4
#define LL 1024
#define HH 8
#define DD 64
#define TT (CC*LL)
#define QSCALE 0.125f
#define EPSV 1e-6f
#define PTOT 2176   // 2080 unique (d<=e) pairs + 96 pad
#define PREAL 2080

// Scratch (static __device__ — no allocation allowed)
__device__ float g_buf[CC*HH*LL];
__device__ float P_buf[(size_t)3*HH*PTOT*DD];
__device__ float z_buf[3*HH*PTOT];
__device__ float zs_buf[3*HH*PTOT];
__device__ float row_buf[TT*HH];
__device__ short2 lut_de[PTOT];
__device__ __nv_bfloat16 Qsh_g[(size_t)TT*HH*DD], Qsl_g[(size_t)TT*HH*DD];
__device__ __nv_bfloat16 Ksh_g[(size_t)TT*HH*DD], Ksl_g[(size_t)TT*HH*DD];
__device__ __nv_bfloat16 Vsh_g[(size_t)TT*HH*DD], Vsl_g[(size_t)TT*HH*DD];
__device__ __nv_bfloat16 Sh_g[(size_t)3*HH*PTOT*DD], Sl_g[(size_t)3*HH*PTOT*DD];

// ---------------------------------------------------------------------------
// mma.sync helpers
// ---------------------------------------------------------------------------
__device__ __forceinline__ uint32_t smem_u32(const void* p) {
    uint32_t a;
    asm("{ .reg .u64 t; cvta.to.shared.u64 t, %1; cvt.u32.u64 %0, t; }"
        : "=r"(a) : "l"(p));
    return a;
}
__device__ __forceinline__ void ldsm4(uint32_t* r, uint32_t a) {
    asm volatile("ldmatrix.sync.aligned.m8n8.x4.shared.b16 {%0,%1,%2,%3}, [%4];"
        : "=r"(r[0]), "=r"(r[1]), "=r"(r[2]), "=r"(r[3]) : "r"(a));
}
__device__ __forceinline__ void ldsm4t(uint32_t* r, uint32_t a) {
    asm volatile("ldmatrix.sync.aligned.m8n8.x4.trans.shared.b16 {%0,%1,%2,%3}, [%4];"
        : "=r"(r[0]), "=r"(r[1]), "=r"(r[2]), "=r"(r[3]) : "r"(a));
}
__device__ __forceinline__ void mma16816(float* d, const uint32_t* a, const uint32_t* b) {
    asm volatile("mma.sync.aligned.m16n8k16.row.col.f32.bf16.bf16.f32 "
        "{%0,%1,%2,%3}, {%4,%5,%6,%7}, {%8,%9}, {%0,%1,%2,%3};"
        : "+f"(d[0]), "+f"(d[1]), "+f"(d[2]), "+f"(d[3])
        : "r"(a[0]), "r"(a[1]), "r"(a[2]), "r"(a[3]), "r"(b[0]), "r"(b[1]));
}
__device__ __forceinline__ void mma16816s(float* d, const uint32_t* a,
                                          uint32_t b0, uint32_t b1) {
    asm volatile("mma.sync.aligned.m16n8k16.row.col.f32.bf16.bf16.f32 "
        "{%0,%1,%2,%3}, {%4,%5,%6,%7}, {%8,%9}, {%0,%1,%2,%3};"
        : "+f"(d[0]), "+f"(d[1]), "+f"(d[2]), "+f"(d[3])
        : "r"(a[0]), "r"(a[1]), "r"(a[2]), "r"(a[3]), "r"(b0), "r"(b1));
}
__device__ __forceinline__ void split_st(__nv_bfloat16* hb, __nv_bfloat16* lb,
                                         int idx, float a) {
    __nv_bfloat16 hv = __float2bfloat16(a);
    hb[idx] = hv;
    lb[idx] = __float2bfloat16(a - __bfloat162float(hv));
}
__device__ __forceinline__ void split2(float x, float y, uint32_t& hi, uint32_t& lo) {
    __nv_bfloat16 xh = __float2bfloat16(x), yh = __float2bfloat16(y);
    __nv_bfloat16 xl = __float2bfloat16(x - __bfloat162float(xh));
    __nv_bfloat16 yl = __float2bfloat16(y - __bfloat162float(yh));
    hi = (uint32_t)*(uint16_t*)&xh | ((uint32_t)*(uint16_t*)&yh << 16);
    lo = (uint32_t)*(uint16_t*)&xl | ((uint32_t)*(uint16_t*)&yl << 16);
}

// ---------------------------------------------------------------------------
// K0a: pre-split Q*scale, K, V into global bf16 hi/lo, [h][t][d] layout.
// ---------------------------------------------------------------------------
__global__ void split_kernel(const float* __restrict__ q,
                             const float* __restrict__ k,
                             const float* __restrict__ v) {
    const int t0 = blockIdx.x * 64, h = blockIdx.y;
    for (int idx = threadIdx.x; idx < 1024; idx += 256) {
        const int l = idx >> 4, d4 = (idx & 15) << 2;
        const int t = t0 + l;
        const size_t gi = ((size_t)t * HH + h) * DD + d4;
        const size_t oo = ((size_t)h * TT + t) * DD + d4;
        uint32_t a0, b0, a1, b1;
        const float4 qv = *(const float4*)&q[gi];
        split2(qv.x * QSCALE, qv.y * QSCALE, a0, b0);
        split2(qv.z * QSCALE, qv.w * QSCALE, a1, b1);
        *(uint2*)&Qsh_g[oo] = make_uint2(a0, a1);
        *(uint2*)&Qsl_g[oo] = make_uint2(b0, b1);
        const float4 kv = *(const float4*)&k[gi];
        split2(kv.x, kv.y, a0, b0);
        split2(kv.z, kv.w, a1, b1);
        *(uint2*)&Ksh_g[oo] = make_uint2(a0, a1);
        *(uint2*)&Ksl_g[oo] = make_uint2(b0, b1);
        const float4 vv = *(const float4*)&v[gi];
        split2(vv.x, vv.y, a0, b0);
        split2(vv.z, vv.w, a1, b1);
        *(uint2*)&Vsh_g[oo] = make_uint2(a0, a1);
        *(uint2*)&Vsl_g[oo] = make_uint2(b0, b1);
    }
}

// ---------------------------------------------------------------------------
// K0b: cumsum per (c,h) + pair-LUT build (last block)
// ---------------------------------------------------------------------------
__global__ void init_kernel(const float* __restrict__ lg) {
    if (blockIdx.x == CC * HH) {
        for (int p = threadIdx.x; p < PTOT; p += 256) {
            short d = 0, e = 0;
            if (p < PREAL) {
                int off = 0, dd = 0;
                while (off + (DD - dd) <= p) { off += DD - dd; dd++; }
                d = (short)dd; e = (short)(dd + (p - off));
            }
            lut_de[p] = make_short2(d, e);
        }
        return;
    }
    int c = blockIdx.x / HH, h = blockIdx.x % HH;
    int t = threadIdx.x;
    float vloc[4];
    float s = 0.f;
#pragma unroll
    for (int i = 0; i < 4; i++) {
        int l = t * 4 + i;
        s += lg[(c * LL + l) * HH + h];
        vloc[i] = s;
    }
    float tot = s;
#pragma unroll
    for (int off = 1; off < 32; off <<= 1) {
        float n = __shfl_up_sync(0xffffffffu, tot, off);
        if ((t & 31) >= off) tot += n;
    }
    __shared__ float wsum[8];
    __shared__ float woff[8];
    if ((t & 31) == 31) wsum[t >> 5] = tot;
    __syncthreads();
    if (t == 0) {
        float a = 0.f;
        for (int w = 0; w < 8; w++) { woff[w] = a; a += wsum[w]; }
    }
    __syncthreads();
    float ex = woff[t >> 5] + (tot - s);
#pragma unroll
    for (int i = 0; i < 4; i++)
        g_buf[(c * HH + h) * LL + t * 4 + i] = ex + vloc[i];
}

// ---------------------------------------------------------------------------
// K1: intra-chunk causal attention via bf16-split mma.sync.
// Heavy tiles launch first (tile = 15 - blockIdx.x) for wave packing.
// ---------------------------------------------------------------------------
__global__ void __launch_bounds__(128) intra_tc_kernel(float* __restrict__ out) {
    __shared__ __align__(16) __nv_bfloat16 Qh[64 * 72], Ql[64 * 72];
    __shared__ __align__(16) __nv_bfloat16 Kh[32 * 72], Kl[32 * 72];
    __shared__ __align__(16) __nv_bfloat16 Vh[32 * 72], Vl[32 * 72];
    __shared__ float eqs[64], eks[32];
    const int tile = 15 - blockIdx.x, h = blockIdx.y, c = blockIdx.z;
    const int tid = threadIdx.x, lane = tid & 31, w = tid >> 5;
    const int l0 = tile * 64;

    {
        const size_t qb = ((size_t)h * TT + c * LL + l0) * DD;
#pragma unroll
        for (int idx = tid; idx < 512; idx += 128) {
            const int l = idx >> 3, u = (idx & 7) * 8;
            *(uint4*)&Qh[l * 72 + u] = *(const uint4*)&Qsh_g[qb + l * 64 + u];
            *(uint4*)&Ql[l * 72 + u] = *(const uint4*)&Qsl_g[qb + l * 64 + u];
        }
    }
    if (tid < 64) eqs[tid] = __expf(g_buf[(c * HH + h) * LL + l0 + tid]);

    const int m0w = w * 16;
    const int r0 = m0w + (lane >> 2);
    const uint32_t QhB = smem_u32(Qh), QlB = smem_u32(Ql);
    const uint32_t KhB = smem_u32(Kh), KlB = smem_u32(Kl);
    const uint32_t VhB = smem_u32(Vh), VlB = smem_u32(Vl);
    const uint32_t aoffQ = ((m0w + (lane & 15)) * 72 + (lane >> 4) * 8) * 2;
    const uint32_t boff = ((lane & 15) * 72 + (lane >> 4) * 8) * 2;

    float oacc[8][4];
#pragma unroll
    for (int i = 0; i < 8; i++)
#pragma unroll
        for (int j = 0; j < 4; j++) oacc[i][j] = 0.f;
    float rs0 = 0.f, rs1 = 0.f;

    const int nst = 2 * (tile + 1);
    for (int st = 0; st < nst; st++) {
        __syncthreads();
        {
            const size_t kb = ((size_t)h * TT + c * LL + st * 32) * DD;
#pragma unroll
            for (int idx = tid; idx < 256; idx += 128) {
                const int l = idx >> 3, u = (idx & 7) * 8;
                const int so = l * 72 + u;
                const size_t go = kb + l * 64 + u;
                const uint4 a = *(const uint4*)&Ksh_g[go];
                const uint4 b = *(const uint4*)&Ksl_g[go];
                const uint4 cc2 = *(const uint4*)&Vsh_g[go];
                const uint4 d = *(const uint4*)&Vsl_g[go];
                *(uint4*)&Kh[so] = a;
                *(uint4*)&Kl[so] = b;
                *(uint4*)&Vh[so] = cc2;
                *(uint4*)&Vl[so] = d;
            }
        }
        if (tid < 32) eks[tid] = __expf(-g_buf[(c * HH + h) * LL + st * 32 + tid]);
        __syncthreads();

        float sc[4][4];
#pragma unroll
        for (int i = 0; i < 4; i++)
#pragma unroll
            for (int j = 0; j < 4; j++) sc[i][j] = 0.f;
#pragma unroll
        for (int kd = 0; kd < 4; kd++) {
            uint32_t ah[4], al[4];
            ldsm4(ah, QhB + aoffQ + kd * 32);
            ldsm4(al, QlB + aoffQ + kd * 32);
#pragma unroll
            for (int ng = 0; ng < 2; ng++) {
                uint32_t kh4[4], kl4[4];
                const uint32_t rb = (uint32_t)(ng * 16 * 72 * 2) + boff + kd * 32;
                ldsm4(kh4, KhB + rb);
                ldsm4(kl4, KlB + rb);
                mma16816s(sc[ng * 2],     ah, kh4[0], kh4[2]);
                mma16816s(sc[ng * 2],     ah, kl4[0], kl4[2]);
                mma16816s(sc[ng * 2],     al, kh4[0], kh4[2]);
                mma16816s(sc[ng * 2 + 1], ah, kh4[1], kh4[3]);
                mma16816s(sc[ng * 2 + 1], ah, kl4[1], kl4[3]);
                mma16816s(sc[ng * 2 + 1], al, kh4[1], kh4[3]);
            }
        }

        const float eq0 = eqs[r0], eq1 = eqs[r0 + 8];
        const int soff = st * 32 - l0;
        uint32_t wah[2][4], wal[2][4];
#pragma unroll
        for (int nt = 0; nt < 4; nt++) {
            const int sA = nt * 8 + 2 * (lane & 3);
            const float ekA = eks[sA], ekB = eks[sA + 1];
            float w00 = eq0 * ekA * sc[nt][0] * sc[nt][0];
            float w01 = eq0 * ekB * sc[nt][1] * sc[nt][1];
            float w10 = eq1 * ekA * sc[nt][2] * sc[nt][2];
            float w11 = eq1 * ekB * sc[nt][3] * sc[nt][3];
            if (soff >= 0) {
                if (r0 < soff + sA) w00 = 0.f;
                if (r0 < soff + sA + 1) w01 = 0.f;
                if (r0 + 8 < soff + sA) w10 = 0.f;
                if (r0 + 8 < soff + sA + 1) w11 = 0.f;
            }
            rs0 += w00 + w01;
            rs1 += w10 + w11;
            const int ks = nt >> 1, hf2 = (nt & 1) * 2;
            split2(w00, w01, wah[ks][hf2], wal[ks][hf2]);
            split2(w10, w11, wah[ks][hf2 + 1], wal[ks][hf2 + 1]);
        }

#pragma unroll
        for (int ks = 0; ks < 2; ks++) {
#pragma unroll
            for (int nv = 0; nv < 4; nv++) {
                uint32_t vh4[4], vl4[4];
                const uint32_t bo = boff + (uint32_t)(ks * 16 * 72 * 2) + nv * 32;
                ldsm4t(vh4, VhB + bo);
                ldsm4t(vl4, VlB + bo);
                mma16816s(oacc[nv * 2],     wah[ks], vh4[0], vh4[1]);
                mma16816s(oacc[nv * 2],     wah[ks], vl4[0], vl4[1]);
                mma16816s(oacc[nv * 2],     wal[ks], vh4[0], vh4[1]);
                mma16816s(oacc[nv * 2 + 1], wah[ks], vh4[2], vh4[3]);
                mma16816s(oacc[nv * 2 + 1], wah[ks], vl4[2], vl4[3]);
                mma16816s(oacc[nv * 2 + 1], wal[ks], vh4[2], vh4[3]);
            }
        }
    }

    rs0 += __shfl_xor_sync(0xffffffffu, rs0, 1);
    rs0 += __shfl_xor_sync(0xffffffffu, rs0, 2);
    rs1 += __shfl_xor_sync(0xffffffffu, rs1, 1);
    rs1 += __shfl_xor_sync(0xffffffffu, rs1, 2);
    const int t0 = c * LL + l0 + r0, t1 = t0 + 8;
    if ((lane & 3) == 0) {
        row_buf[t0 * HH + h] = rs0;
        row_buf[t1 * HH + h] = rs1;
    }
    float* O0 = &out[((size_t)t0 * HH + h) * DD];
    float* O1 = &out[((size_t)t1 * HH + h) * DD];
#pragma unroll
    for (int nt = 0; nt < 8; nt++) {
        const int c2 = nt * 8 + 2 * (lane & 3);
        *(float2*)&O0[c2] = make_float2(oacc[nt][0], oacc[nt][1]);
        *(float2*)&O1[c2] = make_float2(oacc[nt][2], oacc[nt][3]);
    }
}

// ---------------------------------------------------------------------------
// K2: pz via bf16-split mma.sync — R7 shape (256 thr, 8 warps x 16p),
// scalar split_st A-build, occupancy pinned to 3 blocks/SM. grid (17, H, 3).
// ---------------------------------------------------------------------------
__global__ void __launch_bounds__(256, 3) pz_tc_kernel(const float* __restrict__ k) {
    __shared__ float Ks[32 * 67];                           // [l][d] fp32
    __shared__ __align__(16) __nv_bfloat16 Bh[32 * 72];     // V split hi [l][v]
    __shared__ __align__(16) __nv_bfloat16 Bl[32 * 72];
    __shared__ __align__(16) __nv_bfloat16 Ah[128 * 40];    // A split hi [p][l]
    __shared__ __align__(16) __nv_bfloat16 Al[128 * 40];
    __shared__ float wl[32];
    const int bt = blockIdx.x, h = blockIdx.y, c = blockIdx.z;
    const int tid = threadIdx.x, lane = tid & 31, w = tid >> 5;
    const int p0 = bt * 128;
    const short2 de = lut_de[p0 + (tid >> 1)];
    const float m0 = (p0 + (tid >> 1) >= PREAL) ? 0.f
                     : ((de.x == de.y) ? 1.f : 2.f);
    const int lh = (tid & 1) * 16;
    const int pr = tid >> 1;
    const float gend = g_buf[(c * HH + h) * LL + LL - 1];
    float zacc = 0.f;

    float acc[8][4];
#pragma unroll
    for (int i = 0; i < 8; i++)
#pragma unroll
        for (int j = 0; j < 4; j++) acc[i][j] = 0.f;

    const uint32_t AhB = smem_u32(Ah), AlB = smem_u32(Al);
    const uint32_t BhB = smem_u32(Bh), BlB = smem_u32(Bl);
    const int m0w = w * 16;
    const uint32_t aoff = ((m0w + (lane & 15)) * 40 + (lane >> 4) * 8) * 2;
    const uint32_t boff = ((lane & 15) * 72 + (lane >> 4) * 8) * 2;

    for (int lt = 0; lt < 32; lt++) {
        const int l0g = lt * 32;
        __syncthreads();
        {   // stage presplit V + fp32 K
            const size_t vb = ((size_t)h * TT + c * LL + l0g) * DD;
            for (int idx = tid; idx < 256; idx += 256) {
                const int l = idx >> 3, u = (idx & 7) * 8;
                const int so = l * 72 + u;
                const size_t go = vb + l * 64 + u;
                *(uint4*)&Bh[so] = *(const uint4*)&Vsh_g[go];
                *(uint4*)&Bl[so] = *(const uint4*)&Vsl_g[go];
            }
            for (int idx = tid; idx < 512; idx += 256) {
                const int l = idx >> 4, d4 = (idx & 15) << 2;
                const size_t gb = ((size_t)(c * LL + l0g + l) * HH + h) * DD + d4;
                const float4 kv = *(const float4*)&k[gb];
                Ks[l * 67 + d4 + 0] = kv.x;
                Ks[l * 67 + d4 + 1] = kv.y;
                Ks[l * 67 + d4 + 2] = kv.z;
                Ks[l * 67 + d4 + 3] = kv.w;
            }
        }
        if (tid < 32)
            wl[tid] = __expf(gend - g_buf[(c * HH + h) * LL + l0g + tid]);
        __syncthreads();
        // A build: 2 threads per p-row, 16 l each (scalar split stores)
#pragma unroll
        for (int j = 0; j < 16; j++) {
            const int l = lh + j;
            const float a = m0 * wl[l] * Ks[l * 67 + de.x] * Ks[l * 67 + de.y];
            zacc += a;
            split_st(Ah, Al, pr * 40 + l, a);
        }
        __syncthreads();
#pragma unroll
        for (int ks = 0; ks < 2; ks++) {
            uint32_t ah[4], al[4];
            ldsm4(ah, AhB + aoff + ks * 32);
            ldsm4(al, AlB + aoff + ks * 32);
#pragma unroll
            for (int nt2 = 0; nt2 < 4; nt2++) {
                uint32_t bh[4], bl[4];
                const uint32_t bo = boff + ks * (16 * 72 * 2) + nt2 * 32;
                ldsm4t(bh, BhB + bo);
                ldsm4t(bl, BlB + bo);
                mma16816(acc[2 * nt2],     ah, bh);
                mma16816(acc[2 * nt2],     ah, bl);
                mma16816(acc[2 * nt2],     al, bh);
                mma16816(acc[2 * nt2 + 1], ah, bh + 2);
                mma16816(acc[2 * nt2 + 1], ah, bl + 2);
                mma16816(acc[2 * nt2 + 1], al, bh + 2);
            }
        }
    }

    const float zo = zacc + __shfl_xor_sync(0xffffffffu, zacc, 1);
    const size_t pb = (size_t)(c * HH + h) * PTOT + p0;
    if (!(tid & 1)) z_buf[pb + pr] = zo;

    const int r0 = m0w + (lane >> 2);
    float* P0 = &P_buf[(pb + r0) * 64];
    float* P1 = &P_buf[(pb + r0 + 8) * 64];
#pragma unroll
    for (int nt = 0; nt < 8; nt++) {
        const int c2 = nt * 8 + 2 * (lane & 3);
        *(float2*)&P0[c2] = make_float2(acc[nt][0], acc[nt][1]);
        *(float2*)&P1[c2] = make_float2(acc[nt][2], acc[nt][3]);
    }
}

// ---------------------------------------------------------------------------
// K2b: prefix-state combine; emits SPLIT bf16 prefix states directly.
// ---------------------------------------------------------------------------
__global__ void combineP_kernel() {
    const int perh = PTOT * 16;
    int idx = blockIdx.x * 256 + threadIdx.x;
    if (idx >= HH * perh) return;
    int h = idx / perh, r = idx % perh;
    const float gt1 = __expf(g_buf[(1 * HH + h) * LL + LL - 1]);
    const float gt2 = __expf(g_buf[(2 * HH + h) * LL + LL - 1]);
    const float4* P = (const float4*)P_buf;
    const size_t o0 = (size_t)(0 * HH + h) * perh + r;
    const size_t o1 = (size_t)(1 * HH + h) * perh + r;
    const size_t o2 = (size_t)(2 * HH + h) * perh + r;
    const float4 p0 = P[o0], p1 = P[o1], p2 = P[o2];
    float4 s1 = p0;
    float4 s2 = make_float4(gt1 * s1.x + p1.x, gt1 * s1.y + p1.y,
                            gt1 * s1.z + p1.z, gt1 * s1.w + p1.w);
    float4 s3 = make_float4(gt2 * s2.x + p2.x, gt2 * s2.y + p2.y,
                            gt2 * s2.z + p2.z, gt2 * s2.w + p2.w);
    uint32_t a0, b0, a1, b1;
    split2(s1.x, s1.y, a0, b0); split2(s1.z, s1.w, a1, b1);
    *(uint2*)&Sh_g[o0 * 4] = make_uint2(a0, a1);
    *(uint2*)&Sl_g[o0 * 4] = make_uint2(b0, b1);
    split2(s2.x, s2.y, a0, b0); split2(s2.z, s2.w, a1, b1);
    *(uint2*)&Sh_g[o1 * 4] = make_uint2(a0, a1);
    *(uint2*)&Sl_g[o1 * 4] = make_uint2(b0, b1);
    split2(s3.x, s3.y, a0, b0); split2(s3.z, s3.w, a1, b1);
    *(uint2*)&Sh_g[o2 * 4] = make_uint2(a0, a1);
    *(uint2*)&Sl_g[o2 * 4] = make_uint2(b0, b1);
}

__global__ void combineZ_kernel() {
    int idx = blockIdx.x * 256 + threadIdx.x;
    if (idx >= HH * PTOT) return;
    int h = idx / PTOT, r = idx % PTOT;
    const float gt1 = __expf(g_buf[(1 * HH + h) * LL + LL - 1]);
    const float gt2 = __expf(g_buf[(2 * HH + h) * LL + LL - 1]);
    const float p0 = z_buf[(0 * HH + h) * PTOT + r];
    const float p1 = z_buf[(1 * HH + h) * PTOT + r];
    const float p2 = z_buf[(2 * HH + h) * PTOT + r];
    float s1 = p0;
    float s2 = gt1 * s1 + p1;
    float s3 = gt2 * s2 + p2;
    zs_buf[(0 * HH + h) * PTOT + r] = s1;
    zs_buf[(1 * HH + h) * PTOT + r] = s2;
    zs_buf[(2 * HH + h) * PTOT + r] = s3;
}

// ---------------------------------------------------------------------------
// K3: inter via bf16-split mma.sync + finalize (R8 version, kept).
// ---------------------------------------------------------------------------
__global__ void __launch_bounds__(128) inter_tc_kernel(
    const float* __restrict__ q, float* __restrict__ out) {
    const int bx = blockIdx.x, h = blockIdx.y, c = blockIdx.z;
    const int tid = threadIdx.x, lane = tid & 31, w = tid >> 5;
    const int l0 = bx * 64;

    if (c == 0) {
        for (int idx = tid; idx < 1024; idx += 128) {
            int l = idx >> 4, v4 = (idx & 15) << 2;
            const int t_ = l0 + l;
            const float inv = 1.f / fmaxf(row_buf[t_ * HH + h], EPSV);
            float4 ov = *(float4*)&out[((size_t)t_ * HH + h) * DD + v4];
            ov.x *= inv; ov.y *= inv; ov.z *= inv; ov.w *= inv;
            *(float4*)&out[((size_t)t_ * HH + h) * DD + v4] = ov;
        }
        return;
    }

    __shared__ float Qs[64 * 65];
    __shared__ __align__(16) __nv_bfloat16 Ah[64 * 40];
    __shared__ __align__(16) __nv_bfloat16 Al[64 * 40];
    __shared__ __align__(16) __nv_bfloat16 Bh[32 * 72];
    __shared__ __align__(16) __nv_bfloat16 Bl[32 * 72];
    __shared__ float zv[32];
    __shared__ short2 lutS[32];
    __shared__ float denp[128];
    __shared__ float denl[64];

    for (int idx = tid; idx < 1024; idx += 128) {
        int l = idx >> 4, d4 = (idx & 15) << 2;
        float4 qv = *(const float4*)&q[((size_t)(c * LL + l0 + l) * HH + h) * DD + d4];
        Qs[l * 65 + d4 + 0] = qv.x * QSCALE;
        Qs[l * 65 + d4 + 1] = qv.y * QSCALE;
        Qs[l * 65 + d4 + 2] = qv.z * QSCALE;
        Qs[l * 65 + d4 + 3] = qv.w * QSCALE;
    }
    const int lrow = tid >> 1, ph = (tid & 1) * 16;
    const float qdl = __expf(g_buf[(c * HH + h) * LL + l0 + lrow]);
    float dacc = 0.f;

    const int mf = w & 1, nh = w >> 1;
    float acc[2][4][4];
#pragma unroll
    for (int f = 0; f < 2; f++)
#pragma unroll
        for (int i = 0; i < 4; i++)
#pragma unroll
            for (int j = 0; j < 4; j++) acc[f][i][j] = 0.f;

    const size_t Sbase = (size_t)((c - 1) * HH + h) * PTOT * DD;
    const float* zp = &zs_buf[((c - 1) * HH + h) * PTOT];
    const uint32_t AhB = smem_u32(Ah), AlB = smem_u32(Al);
    const uint32_t BhB = smem_u32(Bh), BlB = smem_u32(Bl);
    uint32_t aoff[2];
    aoff[0] = ((mf * 32 + (lane & 15)) * 40 + (lane >> 4) * 8) * 2;
    aoff[1] = aoff[0] + 16 * 40 * 2;
    const uint32_t boff = ((lane & 15) * 72 + (lane >> 4) * 8) * 2;

    for (int pt = 0; pt < PTOT / 32; pt++) {
        const int p0 = pt * 32;
        __syncthreads();
        {
            const size_t sb2 = Sbase + (size_t)p0 * 64;
#pragma unroll
            for (int idx = tid; idx < 256; idx += 128) {
                const int pp = idx >> 3, u = (idx & 7) * 8;
                const int so = pp * 72 + u;
                const size_t go = sb2 + pp * 64 + u;
                *(uint4*)&Bh[so] = *(const uint4*)&Sh_g[go];
                *(uint4*)&Bl[so] = *(const uint4*)&Sl_g[go];
            }
        }
        if (tid < 32) {
            zv[tid] = zp[p0 + tid];
            lutS[tid] = lut_de[p0 + tid];
        }
        __syncthreads();
#pragma unroll
        for (int j = 0; j < 16; j++) {
            const int pp = ph + j;
            const short2 de = lutS[pp];
            const float a = qdl * Qs[lrow * 65 + de.x] * Qs[lrow * 65 + de.y];
            dacc += a * zv[pp];
            split_st(Ah, Al, lrow * 40 + pp, a);
        }
        __syncthreads();
#pragma unroll
        for (int ks = 0; ks < 2; ks++) {
            uint32_t ah0[4], al0[4], ah1[4], al1[4];
            ldsm4(ah0, AhB + aoff[0] + ks * 32);
            ldsm4(al0, AlB + aoff[0] + ks * 32);
            ldsm4(ah1, AhB + aoff[1] + ks * 32);
            ldsm4(al1, AlB + aoff[1] + ks * 32);
#pragma unroll
            for (int t2 = 0; t2 < 2; t2++) {
                const int nt2 = nh * 2 + t2;
                uint32_t bh[4], bl[4];
                const uint32_t bo = boff + ks * (16 * 72 * 2) + nt2 * 32;
                ldsm4t(bh, BhB + bo);
                ldsm4t(bl, BlB + bo);
                mma16816(acc[0][2 * t2],     ah0, bh);
                mma16816(acc[0][2 * t2],     ah0, bl);
                mma16816(acc[0][2 * t2],     al0, bh);
                mma16816(acc[0][2 * t2 + 1], ah0, bh + 2);
                mma16816(acc[0][2 * t2 + 1], ah0, bl + 2);
                mma16816(acc[0][2 * t2 + 1], al0, bh + 2);
                mma16816(acc[1][2 * t2],     ah1, bh);
                mma16816(acc[1][2 * t2],     ah1, bl);
                mma16816(acc[1][2 * t2],     al1, bh);
                mma16816(acc[1][2 * t2 + 1], ah1, bh + 2);
                mma16816(acc[1][2 * t2 + 1], ah1, bl + 2);
                mma16816(acc[1][2 * t2 + 1], al1, bh + 2);
            }
        }
    }

    denp[tid] = dacc;
    __syncthreads();
    if (tid < 64) denl[tid] = denp[2 * tid] + denp[2 * tid + 1];
    __syncthreads();

#pragma unroll
    for (int f = 0; f < 2; f++) {
        const int rl = mf * 32 + f * 16 + (lane >> 2);
        const int t0 = c * LL + l0 + rl, t1 = t0 + 8;
        const float inv0 = 1.f / fmaxf(row_buf[t0 * HH + h] + denl[rl], EPSV);
        const float inv1 = 1.f / fmaxf(row_buf[t1 * HH + h] + denl[rl + 8], EPSV);
        float* O0 = &out[((size_t)t0 * HH + h) * DD];
        float* O1 = &out[((size_t)t1 * HH + h) * DD];
#pragma unroll
        for (int j = 0; j < 4; j++) {
            const int c2 = nh * 32 + j * 8 + 2 * (lane & 3);
            float2 o0 = *(float2*)&O0[c2];
            o0.x = (o0.x + acc[f][j][0]) * inv0;
            o0.y = (o0.y + acc[f][j][1]) * inv0;
            *(float2*)&O0[c2] = o0;
            float2 o1 = *(float2*)&O1[c2];
            o1.x = (o1.x + acc[f][j][2]) * inv1;
            o1.y = (o1.y + acc[f][j][3]) * inv1;
            *(float2*)&O1[c2] = o1;
        }
    }
}

extern "C" void kernel_launch(void* const* d_in, const int* in_sizes, int n_in,
                              void* d_out, int out_size) {
    const float* q = (const float*)d_in[0];
    const float* k = (const float*)d_in[1];
    const float* v = (const float*)d_in[2];
    const float* lg = (const float*)d_in[3];
    float* out = (float*)d_out;

    // Fork the pz->combine chain onto a side stream so it runs concurrently
    // with intra (they are independent). Events make the fork/join part of
    // the captured graph. Stream/events are created per call (kernel_launch
    // is only invoked a handful of times: correctness + capture).
    cudaStream_t s2;
    cudaStreamCreateWithFlags(&s2, cudaStreamNonBlocking);
    cudaEvent_t eA, eB;
    cudaEventCreateWithFlags(&eA, cudaEventDisableTiming);
    cudaEventCreateWithFlags(&eB, cudaEventDisableTiming);

    init_kernel<<<CC * HH + 1, 256>>>(lg);

    dim3 gs(TT / 64, HH);
    split_kernel<<<gs, 256>>>(q, k, v);

    cudaEventRecord(eA, 0);            // fork point: split+init complete
    cudaStreamWaitEvent(s2, eA, 0);

    // side stream: expanded-state chain
    dim3 gp(PTOT / 128, HH, CC - 1);
    pz_tc_kernel<<<gp, 256, 0, s2>>>(k);
    combineP_kernel<<<(HH * PTOT * 16 + 255) / 256, 256, 0, s2>>>();
    combineZ_kernel<<<(HH * PTOT + 255) / 256, 256, 0, s2>>>();
    cudaEventRecord(eB, s2);

    // main stream: intra runs concurrently with the side chain
    dim3 gt(16, HH, CC);
    intra_tc_kernel<<<gt, 128>>>(out);

    cudaStreamWaitEvent(0, eB, 0);     // join before inter
    dim3 gi(16, HH, CC);
    inter_tc_kernel<<<gi, 128>>>(q, out);
}

// round 14
// speedup vs baseline: 1.2130x; 1.1294x over previous
#include <cuda_runtime.h>
#include <cuda_bf16.h>
#include <cstdint>

#define CC 4
#define LL 1024
#define HH 8
#define DD 64
#define TT (CC*LL)
#define QSCALE 0.125f
#define EPSV 1e-6f
#define PTOT 2176   // 2080 unique (d<=e) pairs + 96 pad
#define PREAL 2080

// Scratch (static __device__ — no allocation allowed)
__device__ float g_buf[CC*HH*LL];
__device__ float P_buf[(size_t)3*HH*PTOT*DD];
__device__ float z_buf[3*HH*PTOT];
__device__ float zs_buf[3*HH*PTOT];
__device__ float row_buf[TT*HH];
__device__ short2 lut_de[PTOT];
__device__ __nv_bfloat16 Qsh_g[(size_t)TT*HH*DD], Qsl_g[(size_t)TT*HH*DD];
__device__ __nv_bfloat16 Ksh_g[(size_t)TT*HH*DD], Ksl_g[(size_t)TT*HH*DD];
__device__ __nv_bfloat16 Vsh_g[(size_t)TT*HH*DD], Vsl_g[(size_t)TT*HH*DD];
__device__ __nv_bfloat16 Sh_g[(size_t)3*HH*PTOT*DD], Sl_g[(size_t)3*HH*PTOT*DD];

// ---------------------------------------------------------------------------
// mma.sync helpers
// ---------------------------------------------------------------------------
__device__ __forceinline__ uint32_t smem_u32(const void* p) {
    uint32_t a;
    asm("{ .reg .u64 t; cvta.to.shared.u64 t, %1; cvt.u32.u64 %0, t; }"
        : "=r"(a) : "l"(p));
    return a;
}
__device__ __forceinline__ void ldsm4(uint32_t* r, uint32_t a) {
    asm volatile("ldmatrix.sync.aligned.m8n8.x4.shared.b16 {%0,%1,%2,%3}, [%4];"
        : "=r"(r[0]), "=r"(r[1]), "=r"(r[2]), "=r"(r[3]) : "r"(a));
}
__device__ __forceinline__ void ldsm4t(uint32_t* r, uint32_t a) {
    asm volatile("ldmatrix.sync.aligned.m8n8.x4.trans.shared.b16 {%0,%1,%2,%3}, [%4];"
        : "=r"(r[0]), "=r"(r[1]), "=r"(r[2]), "=r"(r[3]) : "r"(a));
}
__device__ __forceinline__ void mma16816(float* d, const uint32_t* a, const uint32_t* b) {
    asm volatile("mma.sync.aligned.m16n8k16.row.col.f32.bf16.bf16.f32 "
        "{%0,%1,%2,%3}, {%4,%5,%6,%7}, {%8,%9}, {%0,%1,%2,%3};"
        : "+f"(d[0]), "+f"(d[1]), "+f"(d[2]), "+f"(d[3])
        : "r"(a[0]), "r"(a[1]), "r"(a[2]), "r"(a[3]), "r"(b[0]), "r"(b[1]));
}
__device__ __forceinline__ void mma16816s(float* d, const uint32_t* a,
                                          uint32_t b0, uint32_t b1) {
    asm volatile("mma.sync.aligned.m16n8k16.row.col.f32.bf16.bf16.f32 "
        "{%0,%1,%2,%3}, {%4,%5,%6,%7}, {%8,%9}, {%0,%1,%2,%3};"
        : "+f"(d[0]), "+f"(d[1]), "+f"(d[2]), "+f"(d[3])
        : "r"(a[0]), "r"(a[1]), "r"(a[2]), "r"(a[3]), "r"(b0), "r"(b1));
}
__device__ __forceinline__ void split_st(__nv_bfloat16* hb, __nv_bfloat16* lb,
                                         int idx, float a) {
    __nv_bfloat16 hv = __float2bfloat16(a);
    hb[idx] = hv;
    lb[idx] = __float2bfloat16(a - __bfloat162float(hv));
}
__device__ __forceinline__ void split2(float x, float y, uint32_t& hi, uint32_t& lo) {
    __nv_bfloat16 xh = __float2bfloat16(x), yh = __float2bfloat16(y);
    __nv_bfloat16 xl = __float2bfloat16(x - __bfloat162float(xh));
    __nv_bfloat16 yl = __float2bfloat16(y - __bfloat162float(yh));
    hi = (uint32_t)*(uint16_t*)&xh | ((uint32_t)*(uint16_t*)&yh << 16);
    lo = (uint32_t)*(uint16_t*)&xl | ((uint32_t)*(uint16_t*)&yl << 16);
}

// ---------------------------------------------------------------------------
// K0a: pre-split Q*scale, K, V into global bf16 hi/lo, [h][t][d] layout.
// ---------------------------------------------------------------------------
__global__ void split_kernel(const float* __restrict__ q,
                             const float* __restrict__ k,
                             const float* __restrict__ v) {
    const int t0 = blockIdx.x * 64, h = blockIdx.y;
    for (int idx = threadIdx.x; idx < 1024; idx += 256) {
        const int l = idx >> 4, d4 = (idx & 15) << 2;
        const int t = t0 + l;
        const size_t gi = ((size_t)t * HH + h) * DD + d4;
        const size_t oo = ((size_t)h * TT + t) * DD + d4;
        uint32_t a0, b0, a1, b1;
        const float4 qv = *(const float4*)&q[gi];
        split2(qv.x * QSCALE, qv.y * QSCALE, a0, b0);
        split2(qv.z * QSCALE, qv.w * QSCALE, a1, b1);
        *(uint2*)&Qsh_g[oo] = make_uint2(a0, a1);
        *(uint2*)&Qsl_g[oo] = make_uint2(b0, b1);
        const float4 kv = *(const float4*)&k[gi];
        split2(kv.x, kv.y, a0, b0);
        split2(kv.z, kv.w, a1, b1);
        *(uint2*)&Ksh_g[oo] = make_uint2(a0, a1);
        *(uint2*)&Ksl_g[oo] = make_uint2(b0, b1);
        const float4 vv = *(const float4*)&v[gi];
        split2(vv.x, vv.y, a0, b0);
        split2(vv.z, vv.w, a1, b1);
        *(uint2*)&Vsh_g[oo] = make_uint2(a0, a1);
        *(uint2*)&Vsl_g[oo] = make_uint2(b0, b1);
    }
}

// ---------------------------------------------------------------------------
// K0b: cumsum per (c,h) + pair-LUT build (last block)
// ---------------------------------------------------------------------------
__global__ void init_kernel(const float* __restrict__ lg) {
    if (blockIdx.x == CC * HH) {
        for (int p = threadIdx.x; p < PTOT; p += 256) {
            short d = 0, e = 0;
            if (p < PREAL) {
                int off = 0, dd = 0;
                while (off + (DD - dd) <= p) { off += DD - dd; dd++; }
                d = (short)dd; e = (short)(dd + (p - off));
            }
            lut_de[p] = make_short2(d, e);
        }
        return;
    }
    int c = blockIdx.x / HH, h = blockIdx.x % HH;
    int t = threadIdx.x;
    float vloc[4];
    float s = 0.f;
#pragma unroll
    for (int i = 0; i < 4; i++) {
        int l = t * 4 + i;
        s += lg[(c * LL + l) * HH + h];
        vloc[i] = s;
    }
    float tot = s;
#pragma unroll
    for (int off = 1; off < 32; off <<= 1) {
        float n = __shfl_up_sync(0xffffffffu, tot, off);
        if ((t & 31) >= off) tot += n;
    }
    __shared__ float wsum[8];
    __shared__ float woff[8];
    if ((t & 31) == 31) wsum[t >> 5] = tot;
    __syncthreads();
    if (t == 0) {
        float a = 0.f;
        for (int w = 0; w < 8; w++) { woff[w] = a; a += wsum[w]; }
    }
    __syncthreads();
    float ex = woff[t >> 5] + (tot - s);
#pragma unroll
    for (int i = 0; i < 4; i++)
        g_buf[(c * HH + h) * LL + t * 4 + i] = ex + vloc[i];
}

// ---------------------------------------------------------------------------
// K1: intra-chunk causal attention via bf16-split mma.sync.
// Heavy tiles launch first (tile = 15 - blockIdx.x) for wave packing.
// ---------------------------------------------------------------------------
__global__ void __launch_bounds__(128) intra_tc_kernel(float* __restrict__ out) {
    __shared__ __align__(16) __nv_bfloat16 Qh[64 * 72], Ql[64 * 72];
    __shared__ __align__(16) __nv_bfloat16 Kh[32 * 72], Kl[32 * 72];
    __shared__ __align__(16) __nv_bfloat16 Vh[32 * 72], Vl[32 * 72];
    __shared__ float eqs[64], eks[32];
    const int tile = 15 - blockIdx.x, h = blockIdx.y, c = blockIdx.z;
    const int tid = threadIdx.x, lane = tid & 31, w = tid >> 5;
    const int l0 = tile * 64;

    {
        const size_t qb = ((size_t)h * TT + c * LL + l0) * DD;
#pragma unroll
        for (int idx = tid; idx < 512; idx += 128) {
            const int l = idx >> 3, u = (idx & 7) * 8;
            *(uint4*)&Qh[l * 72 + u] = *(const uint4*)&Qsh_g[qb + l * 64 + u];
            *(uint4*)&Ql[l * 72 + u] = *(const uint4*)&Qsl_g[qb + l * 64 + u];
        }
    }
    if (tid < 64) eqs[tid] = __expf(g_buf[(c * HH + h) * LL + l0 + tid]);

    const int m0w = w * 16;
    const int r0 = m0w + (lane >> 2);
    const uint32_t QhB = smem_u32(Qh), QlB = smem_u32(Ql);
    const uint32_t KhB = smem_u32(Kh), KlB = smem_u32(Kl);
    const uint32_t VhB = smem_u32(Vh), VlB = smem_u32(Vl);
    const uint32_t aoffQ = ((m0w + (lane & 15)) * 72 + (lane >> 4) * 8) * 2;
    const uint32_t boff = ((lane & 15) * 72 + (lane >> 4) * 8) * 2;

    float oacc[8][4];
#pragma unroll
    for (int i = 0; i < 8; i++)
#pragma unroll
        for (int j = 0; j < 4; j++) oacc[i][j] = 0.f;
    float rs0 = 0.f, rs1 = 0.f;

    const int nst = 2 * (tile + 1);
    for (int st = 0; st < nst; st++) {
        __syncthreads();
        {
            const size_t kb = ((size_t)h * TT + c * LL + st * 32) * DD;
#pragma unroll
            for (int idx = tid; idx < 256; idx += 128) {
                const int l = idx >> 3, u = (idx & 7) * 8;
                const int so = l * 72 + u;
                const size_t go = kb + l * 64 + u;
                const uint4 a = *(const uint4*)&Ksh_g[go];
                const uint4 b = *(const uint4*)&Ksl_g[go];
                const uint4 cc2 = *(const uint4*)&Vsh_g[go];
                const uint4 d = *(const uint4*)&Vsl_g[go];
                *(uint4*)&Kh[so] = a;
                *(uint4*)&Kl[so] = b;
                *(uint4*)&Vh[so] = cc2;
                *(uint4*)&Vl[so] = d;
            }
        }
        if (tid < 32) eks[tid] = __expf(-g_buf[(c * HH + h) * LL + st * 32 + tid]);
        __syncthreads();

        float sc[4][4];
#pragma unroll
        for (int i = 0; i < 4; i++)
#pragma unroll
            for (int j = 0; j < 4; j++) sc[i][j] = 0.f;
#pragma unroll
        for (int kd = 0; kd < 4; kd++) {
            uint32_t ah[4], al[4];
            ldsm4(ah, QhB + aoffQ + kd * 32);
            ldsm4(al, QlB + aoffQ + kd * 32);
#pragma unroll
            for (int ng = 0; ng < 2; ng++) {
                uint32_t kh4[4], kl4[4];
                const uint32_t rb = (uint32_t)(ng * 16 * 72 * 2) + boff + kd * 32;
                ldsm4(kh4, KhB + rb);
                ldsm4(kl4, KlB + rb);
                mma16816s(sc[ng * 2],     ah, kh4[0], kh4[2]);
                mma16816s(sc[ng * 2],     ah, kl4[0], kl4[2]);
                mma16816s(sc[ng * 2],     al, kh4[0], kh4[2]);
                mma16816s(sc[ng * 2 + 1], ah, kh4[1], kh4[3]);
                mma16816s(sc[ng * 2 + 1], ah, kl4[1], kl4[3]);
                mma16816s(sc[ng * 2 + 1], al, kh4[1], kh4[3]);
            }
        }

        const float eq0 = eqs[r0], eq1 = eqs[r0 + 8];
        const int soff = st * 32 - l0;
        uint32_t wah[2][4], wal[2][4];
#pragma unroll
        for (int nt = 0; nt < 4; nt++) {
            const int sA = nt * 8 + 2 * (lane & 3);
            const float ekA = eks[sA], ekB = eks[sA + 1];
            float w00 = eq0 * ekA * sc[nt][0] * sc[nt][0];
            float w01 = eq0 * ekB * sc[nt][1] * sc[nt][1];
            float w10 = eq1 * ekA * sc[nt][2] * sc[nt][2];
            float w11 = eq1 * ekB * sc[nt][3] * sc[nt][3];
            if (soff >= 0) {
                if (r0 < soff + sA) w00 = 0.f;
                if (r0 < soff + sA + 1) w01 = 0.f;
                if (r0 + 8 < soff + sA) w10 = 0.f;
                if (r0 + 8 < soff + sA + 1) w11 = 0.f;
            }
            rs0 += w00 + w01;
            rs1 += w10 + w11;
            const int ks = nt >> 1, hf2 = (nt & 1) * 2;
            split2(w00, w01, wah[ks][hf2], wal[ks][hf2]);
            split2(w10, w11, wah[ks][hf2 + 1], wal[ks][hf2 + 1]);
        }

#pragma unroll
        for (int ks = 0; ks < 2; ks++) {
#pragma unroll
            for (int nv = 0; nv < 4; nv++) {
                uint32_t vh4[4], vl4[4];
                const uint32_t bo = boff + (uint32_t)(ks * 16 * 72 * 2) + nv * 32;
                ldsm4t(vh4, VhB + bo);
                ldsm4t(vl4, VlB + bo);
                mma16816s(oacc[nv * 2],     wah[ks], vh4[0], vh4[1]);
                mma16816s(oacc[nv * 2],     wah[ks], vl4[0], vl4[1]);
                mma16816s(oacc[nv * 2],     wal[ks], vh4[0], vh4[1]);
                mma16816s(oacc[nv * 2 + 1], wah[ks], vh4[2], vh4[3]);
                mma16816s(oacc[nv * 2 + 1], wah[ks], vl4[2], vl4[3]);
                mma16816s(oacc[nv * 2 + 1], wal[ks], vh4[2], vh4[3]);
            }
        }
    }

    rs0 += __shfl_xor_sync(0xffffffffu, rs0, 1);
    rs0 += __shfl_xor_sync(0xffffffffu, rs0, 2);
    rs1 += __shfl_xor_sync(0xffffffffu, rs1, 1);
    rs1 += __shfl_xor_sync(0xffffffffu, rs1, 2);
    const int t0 = c * LL + l0 + r0, t1 = t0 + 8;
    if ((lane & 3) == 0) {
        row_buf[t0 * HH + h] = rs0;
        row_buf[t1 * HH + h] = rs1;
    }
    float* O0 = &out[((size_t)t0 * HH + h) * DD];
    float* O1 = &out[((size_t)t1 * HH + h) * DD];
#pragma unroll
    for (int nt = 0; nt < 8; nt++) {
        const int c2 = nt * 8 + 2 * (lane & 3);
        *(float2*)&O0[c2] = make_float2(oacc[nt][0], oacc[nt][1]);
        *(float2*)&O1[c2] = make_float2(oacc[nt][2], oacc[nt][3]);
    }
}

// ---------------------------------------------------------------------------
// K2: pz via bf16-split mma.sync — R7 shape (256 thr, 8 warps x 16p),
// scalar split_st A-build, occupancy pinned to 3 blocks/SM. grid (17, H, 3).
// ---------------------------------------------------------------------------
__global__ void __launch_bounds__(256, 3) pz_tc_kernel(const float* __restrict__ k) {
    __shared__ float Ks[32 * 67];                           // [l][d] fp32
    __shared__ __align__(16) __nv_bfloat16 Bh[32 * 72];     // V split hi [l][v]
    __shared__ __align__(16) __nv_bfloat16 Bl[32 * 72];
    __shared__ __align__(16) __nv_bfloat16 Ah[128 * 40];    // A split hi [p][l]
    __shared__ __align__(16) __nv_bfloat16 Al[128 * 40];
    __shared__ float wl[32];
    const int bt = blockIdx.x, h = blockIdx.y, c = blockIdx.z;
    const int tid = threadIdx.x, lane = tid & 31, w = tid >> 5;
    const int p0 = bt * 128;
    const short2 de = lut_de[p0 + (tid >> 1)];
    const float m0 = (p0 + (tid >> 1) >= PREAL) ? 0.f
                     : ((de.x == de.y) ? 1.f : 2.f);
    const int lh = (tid & 1) * 16;
    const int pr = tid >> 1;
    const float gend = g_buf[(c * HH + h) * LL + LL - 1];
    float zacc = 0.f;

    float acc[8][4];
#pragma unroll
    for (int i = 0; i < 8; i++)
#pragma unroll
        for (int j = 0; j < 4; j++) acc[i][j] = 0.f;

    const uint32_t AhB = smem_u32(Ah), AlB = smem_u32(Al);
    const uint32_t BhB = smem_u32(Bh), BlB = smem_u32(Bl);
    const int m0w = w * 16;
    const uint32_t aoff = ((m0w + (lane & 15)) * 40 + (lane >> 4) * 8) * 2;
    const uint32_t boff = ((lane & 15) * 72 + (lane >> 4) * 8) * 2;

    for (int lt = 0; lt < 32; lt++) {
        const int l0g = lt * 32;
        __syncthreads();
        {   // stage presplit V + fp32 K
            const size_t vb = ((size_t)h * TT + c * LL + l0g) * DD;
            for (int idx = tid; idx < 256; idx += 256) {
                const int l = idx >> 3, u = (idx & 7) * 8;
                const int so = l * 72 + u;
                const size_t go = vb + l * 64 + u;
                *(uint4*)&Bh[so] = *(const uint4*)&Vsh_g[go];
                *(uint4*)&Bl[so] = *(const uint4*)&Vsl_g[go];
            }
            for (int idx = tid; idx < 512; idx += 256) {
                const int l = idx >> 4, d4 = (idx & 15) << 2;
                const size_t gb = ((size_t)(c * LL + l0g + l) * HH + h) * DD + d4;
                const float4 kv = *(const float4*)&k[gb];
                Ks[l * 67 + d4 + 0] = kv.x;
                Ks[l * 67 + d4 + 1] = kv.y;
                Ks[l * 67 + d4 + 2] = kv.z;
                Ks[l * 67 + d4 + 3] = kv.w;
            }
        }
        if (tid < 32)
            wl[tid] = __expf(gend - g_buf[(c * HH + h) * LL + l0g + tid]);
        __syncthreads();
        // A build: 2 threads per p-row, 16 l each (scalar split stores)
#pragma unroll
        for (int j = 0; j < 16; j++) {
            const int l = lh + j;
            const float a = m0 * wl[l] * Ks[l * 67 + de.x] * Ks[l * 67 + de.y];
            zacc += a;
            split_st(Ah, Al, pr * 40 + l, a);
        }
        __syncthreads();
#pragma unroll
        for (int ks = 0; ks < 2; ks++) {
            uint32_t ah[4], al[4];
            ldsm4(ah, AhB + aoff + ks * 32);
            ldsm4(al, AlB + aoff + ks * 32);
#pragma unroll
            for (int nt2 = 0; nt2 < 4; nt2++) {
                uint32_t bh[4], bl[4];
                const uint32_t bo = boff + ks * (16 * 72 * 2) + nt2 * 32;
                ldsm4t(bh, BhB + bo);
                ldsm4t(bl, BlB + bo);
                mma16816(acc[2 * nt2],     ah, bh);
                mma16816(acc[2 * nt2],     ah, bl);
                mma16816(acc[2 * nt2],     al, bh);
                mma16816(acc[2 * nt2 + 1], ah, bh + 2);
                mma16816(acc[2 * nt2 + 1], ah, bl + 2);
                mma16816(acc[2 * nt2 + 1], al, bh + 2);
            }
        }
    }

    const float zo = zacc + __shfl_xor_sync(0xffffffffu, zacc, 1);
    const size_t pb = (size_t)(c * HH + h) * PTOT + p0;
    if (!(tid & 1)) z_buf[pb + pr] = zo;

    const int r0 = m0w + (lane >> 2);
    float* P0 = &P_buf[(pb + r0) * 64];
    float* P1 = &P_buf[(pb + r0 + 8) * 64];
#pragma unroll
    for (int nt = 0; nt < 8; nt++) {
        const int c2 = nt * 8 + 2 * (lane & 3);
        *(float2*)&P0[c2] = make_float2(acc[nt][0], acc[nt][1]);
        *(float2*)&P1[c2] = make_float2(acc[nt][2], acc[nt][3]);
    }
}

// ---------------------------------------------------------------------------
// K2b: prefix-state combine; emits SPLIT bf16 prefix states directly.
// ---------------------------------------------------------------------------
__global__ void combineP_kernel() {
    const int perh = PTOT * 16;
    int idx = blockIdx.x * 256 + threadIdx.x;
    if (idx >= HH * perh) return;
    int h = idx / perh, r = idx % perh;
    const float gt1 = __expf(g_buf[(1 * HH + h) * LL + LL - 1]);
    const float gt2 = __expf(g_buf[(2 * HH + h) * LL + LL - 1]);
    const float4* P = (const float4*)P_buf;
    const size_t o0 = (size_t)(0 * HH + h) * perh + r;
    const size_t o1 = (size_t)(1 * HH + h) * perh + r;
    const size_t o2 = (size_t)(2 * HH + h) * perh + r;
    const float4 p0 = P[o0], p1 = P[o1], p2 = P[o2];
    float4 s1 = p0;
    float4 s2 = make_float4(gt1 * s1.x + p1.x, gt1 * s1.y + p1.y,
                            gt1 * s1.z + p1.z, gt1 * s1.w + p1.w);
    float4 s3 = make_float4(gt2 * s2.x + p2.x, gt2 * s2.y + p2.y,
                            gt2 * s2.z + p2.z, gt2 * s2.w + p2.w);
    uint32_t a0, b0, a1, b1;
    split2(s1.x, s1.y, a0, b0); split2(s1.z, s1.w, a1, b1);
    *(uint2*)&Sh_g[o0 * 4] = make_uint2(a0, a1);
    *(uint2*)&Sl_g[o0 * 4] = make_uint2(b0, b1);
    split2(s2.x, s2.y, a0, b0); split2(s2.z, s2.w, a1, b1);
    *(uint2*)&Sh_g[o1 * 4] = make_uint2(a0, a1);
    *(uint2*)&Sl_g[o1 * 4] = make_uint2(b0, b1);
    split2(s3.x, s3.y, a0, b0); split2(s3.z, s3.w, a1, b1);
    *(uint2*)&Sh_g[o2 * 4] = make_uint2(a0, a1);
    *(uint2*)&Sl_g[o2 * 4] = make_uint2(b0, b1);
}

__global__ void combineZ_kernel() {
    int idx = blockIdx.x * 256 + threadIdx.x;
    if (idx >= HH * PTOT) return;
    int h = idx / PTOT, r = idx % PTOT;
    const float gt1 = __expf(g_buf[(1 * HH + h) * LL + LL - 1]);
    const float gt2 = __expf(g_buf[(2 * HH + h) * LL + LL - 1]);
    const float p0 = z_buf[(0 * HH + h) * PTOT + r];
    const float p1 = z_buf[(1 * HH + h) * PTOT + r];
    const float p2 = z_buf[(2 * HH + h) * PTOT + r];
    float s1 = p0;
    float s2 = gt1 * s1 + p1;
    float s3 = gt2 * s2 + p2;
    zs_buf[(0 * HH + h) * PTOT + r] = s1;
    zs_buf[(1 * HH + h) * PTOT + r] = s2;
    zs_buf[(2 * HH + h) * PTOT + r] = s3;
}

// ---------------------------------------------------------------------------
// K3: inter via bf16-split mma.sync + finalize. c = blockIdx.z + cbase so the
// c=0 finalize can launch separately (it needs only intra, not the combines).
// ---------------------------------------------------------------------------
__global__ void __launch_bounds__(128) inter_tc_kernel(
    const float* __restrict__ q, float* __restrict__ out, int cbase) {
    const int bx = blockIdx.x, h = blockIdx.y, c = blockIdx.z + cbase;
    const int tid = threadIdx.x, lane = tid & 31, w = tid >> 5;
    const int l0 = bx * 64;

    if (c == 0) {
        for (int idx = tid; idx < 1024; idx += 128) {
            int l = idx >> 4, v4 = (idx & 15) << 2;
            const int t_ = l0 + l;
            const float inv = 1.f / fmaxf(row_buf[t_ * HH + h], EPSV);
            float4 ov = *(float4*)&out[((size_t)t_ * HH + h) * DD + v4];
            ov.x *= inv; ov.y *= inv; ov.z *= inv; ov.w *= inv;
            *(float4*)&out[((size_t)t_ * HH + h) * DD + v4] = ov;
        }
        return;
    }

    __shared__ float Qs[64 * 65];
    __shared__ __align__(16) __nv_bfloat16 Ah[64 * 40];
    __shared__ __align__(16) __nv_bfloat16 Al[64 * 40];
    __shared__ __align__(16) __nv_bfloat16 Bh[32 * 72];
    __shared__ __align__(16) __nv_bfloat16 Bl[32 * 72];
    __shared__ float zv[32];
    __shared__ short2 lutS[32];
    __shared__ float denp[128];
    __shared__ float denl[64];

    for (int idx = tid; idx < 1024; idx += 128) {
        int l = idx >> 4, d4 = (idx & 15) << 2;
        float4 qv = *(const float4*)&q[((size_t)(c * LL + l0 + l) * HH + h) * DD + d4];
        Qs[l * 65 + d4 + 0] = qv.x * QSCALE;
        Qs[l * 65 + d4 + 1] = qv.y * QSCALE;
        Qs[l * 65 + d4 + 2] = qv.z * QSCALE;
        Qs[l * 65 + d4 + 3] = qv.w * QSCALE;
    }
    const int lrow = tid >> 1, ph = (tid & 1) * 16;
    const float qdl = __expf(g_buf[(c * HH + h) * LL + l0 + lrow]);
    float dacc = 0.f;

    const int mf = w & 1, nh = w >> 1;
    float acc[2][4][4];
#pragma unroll
    for (int f = 0; f < 2; f++)
#pragma unroll
        for (int i = 0; i < 4; i++)
#pragma unroll
            for (int j = 0; j < 4; j++) acc[f][i][j] = 0.f;

    const size_t Sbase = (size_t)((c - 1) * HH + h) * PTOT * DD;
    const float* zp = &zs_buf[((c - 1) * HH + h) * PTOT];
    const uint32_t AhB = smem_u32(Ah), AlB = smem_u32(Al);
    const uint32_t BhB = smem_u32(Bh), BlB = smem_u32(Bl);
    uint32_t aoff[2];
    aoff[0] = ((mf * 32 + (lane & 15)) * 40 + (lane >> 4) * 8) * 2;
    aoff[1] = aoff[0] + 16 * 40 * 2;
    const uint32_t boff = ((lane & 15) * 72 + (lane >> 4) * 8) * 2;

    for (int pt = 0; pt < PTOT / 32; pt++) {
        const int p0 = pt * 32;
        __syncthreads();
        {
            const size_t sb2 = Sbase + (size_t)p0 * 64;
#pragma unroll
            for (int idx = tid; idx < 256; idx += 128) {
                const int pp = idx >> 3, u = (idx & 7) * 8;
                const int so = pp * 72 + u;
                const size_t go = sb2 + pp * 64 + u;
                *(uint4*)&Bh[so] = *(const uint4*)&Sh_g[go];
                *(uint4*)&Bl[so] = *(const uint4*)&Sl_g[go];
            }
        }
        if (tid < 32) {
            zv[tid] = zp[p0 + tid];
            lutS[tid] = lut_de[p0 + tid];
        }
        __syncthreads();
#pragma unroll
        for (int j = 0; j < 16; j++) {
            const int pp = ph + j;
            const short2 de = lutS[pp];
            const float a = qdl * Qs[lrow * 65 + de.x] * Qs[lrow * 65 + de.y];
            dacc += a * zv[pp];
            split_st(Ah, Al, lrow * 40 + pp, a);
        }
        __syncthreads();
#pragma unroll
        for (int ks = 0; ks < 2; ks++) {
            uint32_t ah0[4], al0[4], ah1[4], al1[4];
            ldsm4(ah0, AhB + aoff[0] + ks * 32);
            ldsm4(al0, AlB + aoff[0] + ks * 32);
            ldsm4(ah1, AhB + aoff[1] + ks * 32);
            ldsm4(al1, AlB + aoff[1] + ks * 32);
#pragma unroll
            for (int t2 = 0; t2 < 2; t2++) {
                const int nt2 = nh * 2 + t2;
                uint32_t bh[4], bl[4];
                const uint32_t bo = boff + ks * (16 * 72 * 2) + nt2 * 32;
                ldsm4t(bh, BhB + bo);
                ldsm4t(bl, BlB + bo);
                mma16816(acc[0][2 * t2],     ah0, bh);
                mma16816(acc[0][2 * t2],     ah0, bl);
                mma16816(acc[0][2 * t2],     al0, bh);
                mma16816(acc[0][2 * t2 + 1], ah0, bh + 2);
                mma16816(acc[0][2 * t2 + 1], ah0, bl + 2);
                mma16816(acc[0][2 * t2 + 1], al0, bh + 2);
                mma16816(acc[1][2 * t2],     ah1, bh);
                mma16816(acc[1][2 * t2],     ah1, bl);
                mma16816(acc[1][2 * t2],     al1, bh);
                mma16816(acc[1][2 * t2 + 1], ah1, bh + 2);
                mma16816(acc[1][2 * t2 + 1], ah1, bl + 2);
                mma16816(acc[1][2 * t2 + 1], al1, bh + 2);
            }
        }
    }

    denp[tid] = dacc;
    __syncthreads();
    if (tid < 64) denl[tid] = denp[2 * tid] + denp[2 * tid + 1];
    __syncthreads();

#pragma unroll
    for (int f = 0; f < 2; f++) {
        const int rl = mf * 32 + f * 16 + (lane >> 2);
        const int t0 = c * LL + l0 + rl, t1 = t0 + 8;
        const float inv0 = 1.f / fmaxf(row_buf[t0 * HH + h] + denl[rl], EPSV);
        const float inv1 = 1.f / fmaxf(row_buf[t1 * HH + h] + denl[rl + 8], EPSV);
        float* O0 = &out[((size_t)t0 * HH + h) * DD];
        float* O1 = &out[((size_t)t1 * HH + h) * DD];
#pragma unroll
        for (int j = 0; j < 4; j++) {
            const int c2 = nh * 32 + j * 8 + 2 * (lane & 3);
            float2 o0 = *(float2*)&O0[c2];
            o0.x = (o0.x + acc[f][j][0]) * inv0;
            o0.y = (o0.y + acc[f][j][1]) * inv0;
            *(float2*)&O0[c2] = o0;
            float2 o1 = *(float2*)&O1[c2];
            o1.x = (o1.x + acc[f][j][2]) * inv1;
            o1.y = (o1.y + acc[f][j][3]) * inv1;
            *(float2*)&O1[c2] = o1;
        }
    }
}

extern "C" void kernel_launch(void* const* d_in, const int* in_sizes, int n_in,
                              void* d_out, int out_size) {
    const float* q = (const float*)d_in[0];
    const float* k = (const float*)d_in[1];
    const float* v = (const float*)d_in[2];
    const float* lg = (const float*)d_in[3];
    float* out = (float*)d_out;

    cudaStream_t s2;
    cudaStreamCreateWithFlags(&s2, cudaStreamNonBlocking);
    cudaEvent_t eA, eB;
    cudaEventCreateWithFlags(&eA, cudaEventDisableTiming);
    cudaEventCreateWithFlags(&eB, cudaEventDisableTiming);

    init_kernel<<<CC * HH + 1, 256>>>(lg);

    dim3 gs(TT / 64, HH);
    split_kernel<<<gs, 256>>>(q, k, v);

    cudaEventRecord(eA, 0);            // fork point: split+init complete
    cudaStreamWaitEvent(s2, eA, 0);

    // main stream FIRST: intra occupies SMs; pz blocks backfill as intra drains
    dim3 gt(16, HH, CC);
    intra_tc_kernel<<<gt, 128>>>(out);

    // side stream: expanded-state chain (concurrent with intra)
    dim3 gp(PTOT / 128, HH, CC - 1);
    pz_tc_kernel<<<gp, 256, 0, s2>>>(k);
    combineP_kernel<<<(HH * PTOT * 16 + 255) / 256, 256, 0, s2>>>();
    combineZ_kernel<<<(HH * PTOT + 255) / 256, 256, 0, s2>>>();
    cudaEventRecord(eB, s2);

    // c=0 finalize needs only intra -> run on main stream during side chain
    dim3 gf(16, HH, 1);
    inter_tc_kernel<<<gf, 128>>>(q, out, 0);

    cudaStreamWaitEvent(0, eB, 0);     // join before c=1..3
    dim3 gi(16, HH, CC - 1);
    inter_tc_kernel<<<gi, 128>>>(q, out, 1);
}